// round 13
// baseline (speedup 1.0000x reference)
#include <cuda_runtime.h>
#include <cuda_bf16.h>
#include <math.h>
#include <stdint.h>

#define N_NODES 50000
#define N_EDGES 600000
#define N_PAD   50048   // 391*128
#define IN_CH   128
#define HID1    256
#define HID2    128
#define SCAN_BLKS 196   // ceil(50000/256)

// ---------------- device scratch ----------------
// g_counts is zero at every call start: static zero-init on load, re-zeroed by
// k_agg3 at the end of every call.
__device__ int   g_counts[N_NODES];
__device__ int   g_rowptr[N_NODES + 1];
__device__ int   g_cursor[N_NODES];
__device__ float g_dinv[N_NODES];
__device__ int   g_col[N_EDGES];
__device__ int   g_bsum[SCAN_BLKS];
__device__ int   g_boff[SCAN_BLKS];

__device__ __align__(16) __nv_bfloat16 g_a0_hi[(size_t)N_PAD * 128];
__device__ __align__(16) __nv_bfloat16 g_a0_lo[(size_t)N_PAD * 128];
__device__ __align__(16) __nv_bfloat16 g_wt1_hi[256 * 128];
__device__ __align__(16) __nv_bfloat16 g_wt1_lo[256 * 128];
__device__ __align__(16) __nv_bfloat16 g_wt2_hi[128 * 256];
__device__ __align__(16) __nv_bfloat16 g_wt2_lo[128 * 256];
__device__ float g_hs2[(size_t)N_NODES * 128];
__device__ float g_hs3[(size_t)N_NODES * 2];

// ---------------- degree count (4 edges/thread, MLP=4) + fused weight split ----------------
__global__ void k_count(const int* __restrict__ dst,
                        const float* __restrict__ W1,
                        const float* __restrict__ W2) {
    int t = blockIdx.x * blockDim.x + threadIdx.x;

    // fused W1/W2 split+transpose (independent of edges; first 65536 threads)
    if (t < 128 * 256) {
        int k = t >> 8, m = t & 255;              // W1[k][m], K=128, M=256
        float v = W1[t];
        __nv_bfloat16 h = __float2bfloat16_rn(v);
        __nv_bfloat16 l = __float2bfloat16_rn(v - __bfloat162float(h));
        g_wt1_hi[m * 128 + k] = h;
        g_wt1_lo[m * 128 + k] = l;
    } else if (t < 2 * 128 * 256) {
        int j = t - 128 * 256;
        int k = j >> 7, m = j & 127;              // W2[k][m], K=256, M=128
        float v = W2[j];
        __nv_bfloat16 h = __float2bfloat16_rn(v);
        __nv_bfloat16 l = __float2bfloat16_rn(v - __bfloat162float(h));
        g_wt2_hi[m * 256 + k] = h;
        g_wt2_lo[m * 256 + k] = l;
    }

    if (t * 4 >= N_EDGES) return;
    int4 d4 = *(const int4*)&dst[t * 4];
    atomicAdd(&g_counts[d4.x], 1);
    atomicAdd(&g_counts[d4.y], 1);
    atomicAdd(&g_counts[d4.z], 1);
    atomicAdd(&g_counts[d4.w], 1);
}

// ---------------- 3-phase scan ----------------
__global__ __launch_bounds__(256) void k_scan1() {
    __shared__ int sh[256];
    int b = blockIdx.x, t = threadIdx.x;
    int i = b * 256 + t;
    int v = (i < N_NODES) ? g_counts[i] : 0;
    sh[t] = v;
    __syncthreads();
    #pragma unroll
    for (int off = 1; off < 256; off <<= 1) {
        int u = (t >= off) ? sh[t - off] : 0;
        __syncthreads();
        sh[t] += u;
        __syncthreads();
    }
    if (i < N_NODES) g_rowptr[i + 1] = sh[t];
    if (t == 255) g_bsum[b] = sh[255];
}

__global__ __launch_bounds__(256) void k_scan2() {
    __shared__ int sh[256];
    int t = threadIdx.x;
    int v = (t < SCAN_BLKS) ? g_bsum[t] : 0;
    sh[t] = v;
    __syncthreads();
    #pragma unroll
    for (int off = 1; off < 256; off <<= 1) {
        int u = (t >= off) ? sh[t - off] : 0;
        __syncthreads();
        sh[t] += u;
        __syncthreads();
    }
    if (t < SCAN_BLKS) g_boff[t] = sh[t] - v;  // exclusive
}

__global__ __launch_bounds__(256) void k_scan3() {
    int b = blockIdx.x, t = threadIdx.x;
    int i = b * 256 + t;
    if (i < N_NODES) {
        int rp1 = g_rowptr[i + 1] + g_boff[b];
        g_rowptr[i + 1] = rp1;
        int c = g_counts[i];
        g_cursor[i] = rp1 - c;
        g_dinv[i] = rsqrtf((float)(c + 1));
    }
    if (i == 0) g_rowptr[0] = 0;
}

// ---------------- CSR fill, 4 edges/thread (MLP=4 atomics) ----------------
__global__ void k_fill(const int* __restrict__ src,
                       const int* __restrict__ dst) {
    int t = blockIdx.x * blockDim.x + threadIdx.x;
    if (t * 4 >= N_EDGES) return;
    int4 s4 = *(const int4*)&src[t * 4];
    int4 d4 = *(const int4*)&dst[t * 4];
    int p0 = atomicAdd(&g_cursor[d4.x], 1);
    int p1 = atomicAdd(&g_cursor[d4.y], 1);
    int p2 = atomicAdd(&g_cursor[d4.z], 1);
    int p3 = atomicAdd(&g_cursor[d4.w], 1);
    g_col[p0] = s4.x;
    g_col[p1] = s4.y;
    g_col[p2] = s4.z;
    g_col[p3] = s4.w;
}

// ---------------- helpers ----------------
__device__ __forceinline__ void bf16_split2(float a, float b, uint32_t& hi, uint32_t& lo) {
    __nv_bfloat162 h = __floats2bfloat162_rn(a, b);
    hi = *(uint32_t*)&h;
    float ra = a - __bfloat162float(h.x);
    float rb = b - __bfloat162float(h.y);
    __nv_bfloat162 l = __floats2bfloat162_rn(ra, rb);
    lo = *(uint32_t*)&l;
}

__device__ __forceinline__ void mma_bf16(float* c, uint32_t a0, uint32_t a1,
                                         uint32_t a2, uint32_t a3,
                                         uint32_t b0, uint32_t b1) {
    asm volatile(
        "mma.sync.aligned.m16n8k16.row.col.f32.bf16.bf16.f32 "
        "{%0,%1,%2,%3}, {%4,%5,%6,%7}, {%8,%9}, {%0,%1,%2,%3};"
        : "+f"(c[0]), "+f"(c[1]), "+f"(c[2]), "+f"(c[3])
        : "r"(a0), "r"(a1), "r"(a2), "r"(a3), "r"(b0), "r"(b1));
}

__device__ __forceinline__ void cp16(uint32_t saddr, const void* gptr) {
    asm volatile("cp.async.ca.shared.global [%0], [%1], 16;" :: "r"(saddr), "l"(gptr));
}

// ---------------- fused GEMM1+GEMM2 (3xBF16 mma.sync, 256 threads — R11 best) ----------------
#define AS2 68
#define HS2 132
#define OFF_AL   (128 * AS2)
#define OFF_H1H  (2 * 128 * AS2)
#define OFF_H1L  (OFF_H1H + 128 * HS2)
#define OFF_STG  (OFF_H1L + 128 * HS2)
#define STG_SZ   (2 * 128 * 12)
#define SMEM_U32 (OFF_STG + 2 * STG_SZ)

__global__ __launch_bounds__(256) void k_gemm12(const __nv_bfloat16* __restrict__ a_hi,
                                                const __nv_bfloat16* __restrict__ a_lo,
                                                const __nv_bfloat16* __restrict__ w1h,
                                                const __nv_bfloat16* __restrict__ w1l,
                                                const __nv_bfloat16* __restrict__ w2h,
                                                const __nv_bfloat16* __restrict__ w2l,
                                                const float* __restrict__ b1,
                                                float* __restrict__ hs2) {
    extern __shared__ __align__(16) uint32_t sm[];

    const int tid  = threadIdx.x;
    const int lane = tid & 31;
    const int warp = tid >> 5;
    const int gid  = lane >> 2;
    const int tig  = lane & 3;
    const int warpM = warp & 3;
    const int warpN = warp >> 2;
    const int rowBase = blockIdx.x * 128;

    const uint32_t sb = (uint32_t)__cvta_generic_to_shared(sm);

    for (int u = tid; u < 4096; u += 256) {
        int p = u >> 11;
        int v = u & 2047;
        int r = v >> 4, ch = v & 15;
        const __nv_bfloat16* g = (p ? a_lo : a_hi) + (size_t)(rowBase + r) * 128 + ch * 8;
        uint32_t d = sb + (uint32_t)(((p ? OFF_AL : 0) + r * AS2 + ch * 4) << 2);
        cp16(d, g);
    }

    auto loadB = [&](int s, const __nv_bfloat16* bh, const __nv_bfloat16* bl,
                     int mBase, int Kb, int kBase) {
        int r = tid >> 1, ch = tid & 1;
        size_t go = (size_t)(mBase + r) * Kb + kBase + ch * 8;
        uint32_t d = sb + (uint32_t)((OFF_STG + s * STG_SZ + r * 12 + ch * 4) << 2);
        cp16(d, bh + go);
        cp16(d + (uint32_t)((128 * 12) << 2), bl + go);
    };

    float acc[2][8][4];

    // =================== phase 1: two column blocks of h1 ===================
    #pragma unroll 1
    for (int cb = 0; cb < 2; cb++) {
        #pragma unroll
        for (int mt = 0; mt < 2; mt++)
            #pragma unroll
            for (int nt = 0; nt < 8; nt++)
                #pragma unroll
                for (int j = 0; j < 4; j++) acc[mt][nt][j] = 0.f;

        loadB(0, w1h, w1l, cb * 128, 128, 0);
        asm volatile("cp.async.commit_group;");

        #pragma unroll 1
        for (int i = 0; i < 8; i++) {
            if (i < 7) {
                loadB((i + 1) & 1, w1h, w1l, cb * 128, 128, (i + 1) * 16);
                asm volatile("cp.async.commit_group;");
                asm volatile("cp.async.wait_group 1;");
            } else {
                asm volatile("cp.async.wait_group 0;");
            }
            __syncthreads();

            const uint32_t* Bh = &sm[OFF_STG + (i & 1) * STG_SZ];
            const uint32_t* Bl = Bh + 128 * 12;
            const int ks = i * 8;

            uint32_t ahi[2][4], alo[2][4];
            #pragma unroll
            for (int mt = 0; mt < 2; mt++) {
                int r0 = warpM * 32 + mt * 16 + gid;
                ahi[mt][0] = sm[r0 * AS2 + ks + tig];
                ahi[mt][1] = sm[(r0 + 8) * AS2 + ks + tig];
                ahi[mt][2] = sm[r0 * AS2 + ks + tig + 4];
                ahi[mt][3] = sm[(r0 + 8) * AS2 + ks + tig + 4];
                alo[mt][0] = sm[OFF_AL + r0 * AS2 + ks + tig];
                alo[mt][1] = sm[OFF_AL + (r0 + 8) * AS2 + ks + tig];
                alo[mt][2] = sm[OFF_AL + r0 * AS2 + ks + tig + 4];
                alo[mt][3] = sm[OFF_AL + (r0 + 8) * AS2 + ks + tig + 4];
            }
            #pragma unroll
            for (int nt = 0; nt < 8; nt++) {
                int c0 = warpN * 64 + nt * 8 + gid;
                uint32_t bh0 = Bh[c0 * 12 + tig], bh1 = Bh[c0 * 12 + tig + 4];
                uint32_t bl0 = Bl[c0 * 12 + tig], bl1 = Bl[c0 * 12 + tig + 4];
                #pragma unroll
                for (int mt = 0; mt < 2; mt++) {
                    mma_bf16(acc[mt][nt], ahi[mt][0], ahi[mt][1], ahi[mt][2], ahi[mt][3], bh0, bh1);
                    mma_bf16(acc[mt][nt], ahi[mt][0], ahi[mt][1], ahi[mt][2], ahi[mt][3], bl0, bl1);
                    mma_bf16(acc[mt][nt], alo[mt][0], alo[mt][1], alo[mt][2], alo[mt][3], bh0, bh1);
                }
            }
            __syncthreads();
        }

        #pragma unroll
        for (int mt = 0; mt < 2; mt++) {
            int rl = warpM * 32 + mt * 16 + gid;
            #pragma unroll
            for (int nt = 0; nt < 8; nt++) {
                int col = cb * 128 + warpN * 64 + nt * 8 + 2 * tig;
                int cidx = col >> 1;
                float bb0 = b1[col], bb1 = b1[col + 1];
                float* c = acc[mt][nt];
                uint32_t h, l;
                float v0 = fmaxf(c[0] + bb0, 0.f), v1 = fmaxf(c[1] + bb1, 0.f);
                bf16_split2(v0, v1, h, l);
                sm[OFF_H1H + rl * HS2 + cidx] = h;
                sm[OFF_H1L + rl * HS2 + cidx] = l;
                v0 = fmaxf(c[2] + bb0, 0.f); v1 = fmaxf(c[3] + bb1, 0.f);
                bf16_split2(v0, v1, h, l);
                sm[OFF_H1H + (rl + 8) * HS2 + cidx] = h;
                sm[OFF_H1L + (rl + 8) * HS2 + cidx] = l;
            }
        }
    }

    // =================== phase 2: hs2 = dinv * (h1 @ W2) ===================
    #pragma unroll
    for (int mt = 0; mt < 2; mt++)
        #pragma unroll
        for (int nt = 0; nt < 8; nt++)
            #pragma unroll
            for (int j = 0; j < 4; j++) acc[mt][nt][j] = 0.f;

    loadB(0, w2h, w2l, 0, 256, 0);
    asm volatile("cp.async.commit_group;");

    #pragma unroll 1
    for (int i = 0; i < 16; i++) {
        if (i < 15) {
            loadB((i + 1) & 1, w2h, w2l, 0, 256, (i + 1) * 16);
            asm volatile("cp.async.commit_group;");
            asm volatile("cp.async.wait_group 1;");
        } else {
            asm volatile("cp.async.wait_group 0;");
        }
        __syncthreads();

        const uint32_t* Bh = &sm[OFF_STG + (i & 1) * STG_SZ];
        const uint32_t* Bl = Bh + 128 * 12;
        const int ks = i * 8;

        uint32_t ahi[2][4], alo[2][4];
        #pragma unroll
        for (int mt = 0; mt < 2; mt++) {
            int r0 = warpM * 32 + mt * 16 + gid;
            ahi[mt][0] = sm[OFF_H1H + r0 * HS2 + ks + tig];
            ahi[mt][1] = sm[OFF_H1H + (r0 + 8) * HS2 + ks + tig];
            ahi[mt][2] = sm[OFF_H1H + r0 * HS2 + ks + tig + 4];
            ahi[mt][3] = sm[OFF_H1H + (r0 + 8) * HS2 + ks + tig + 4];
            alo[mt][0] = sm[OFF_H1L + r0 * HS2 + ks + tig];
            alo[mt][1] = sm[OFF_H1L + (r0 + 8) * HS2 + ks + tig];
            alo[mt][2] = sm[OFF_H1L + r0 * HS2 + ks + tig + 4];
            alo[mt][3] = sm[OFF_H1L + (r0 + 8) * HS2 + ks + tig + 4];
        }
        #pragma unroll
        for (int nt = 0; nt < 8; nt++) {
            int c0 = warpN * 64 + nt * 8 + gid;
            uint32_t bh0 = Bh[c0 * 12 + tig], bh1 = Bh[c0 * 12 + tig + 4];
            uint32_t bl0 = Bl[c0 * 12 + tig], bl1 = Bl[c0 * 12 + tig + 4];
            #pragma unroll
            for (int mt = 0; mt < 2; mt++) {
                mma_bf16(acc[mt][nt], ahi[mt][0], ahi[mt][1], ahi[mt][2], ahi[mt][3], bh0, bh1);
                mma_bf16(acc[mt][nt], ahi[mt][0], ahi[mt][1], ahi[mt][2], ahi[mt][3], bl0, bl1);
                mma_bf16(acc[mt][nt], alo[mt][0], alo[mt][1], alo[mt][2], alo[mt][3], bh0, bh1);
            }
        }
        __syncthreads();
    }

    #pragma unroll
    for (int mt = 0; mt < 2; mt++) {
        int r0 = rowBase + warpM * 32 + mt * 16 + gid;
        #pragma unroll
        for (int nt = 0; nt < 8; nt++) {
            int col = warpN * 64 + nt * 8 + 2 * tig;
            float* c = acc[mt][nt];
            if (r0 < N_NODES) {
                float d = g_dinv[r0];
                *(float2*)&hs2[(size_t)r0 * 128 + col] = make_float2(c[0] * d, c[1] * d);
            }
            if (r0 + 8 < N_NODES) {
                float d = g_dinv[r0 + 8];
                *(float2*)&hs2[(size_t)(r0 + 8) * 128 + col] = make_float2(c[2] * d, c[3] * d);
            }
        }
    }
}

// ---------------- layer-0 aggregation -> split bf16 planes (2-wide) ----------------
__global__ __launch_bounds__(256) void k_agg0(const float* __restrict__ x) {
    int node = (blockIdx.x * blockDim.x + threadIdx.x) >> 5;
    int lane = threadIdx.x & 31;
    if (node >= N_NODES) return;

    float dself = g_dinv[node];
    float4 acc = *(const float4*)&x[(size_t)node * 128 + lane * 4];
    acc.x *= dself; acc.y *= dself; acc.z *= dself; acc.w *= dself;

    int e = g_rowptr[node], eEnd = g_rowptr[node + 1];
    for (; e + 1 < eEnd; e += 2) {
        int s0 = g_col[e], s1 = g_col[e + 1];
        float d0 = g_dinv[s0], d1 = g_dinv[s1];
        float4 x0 = *(const float4*)&x[(size_t)s0 * 128 + lane * 4];
        float4 x1 = *(const float4*)&x[(size_t)s1 * 128 + lane * 4];
        acc.x += x0.x * d0 + x1.x * d1;
        acc.y += x0.y * d0 + x1.y * d1;
        acc.z += x0.z * d0 + x1.z * d1;
        acc.w += x0.w * d0 + x1.w * d1;
    }
    if (e < eEnd) {
        int s0 = g_col[e];
        float d0 = g_dinv[s0];
        float4 x0 = *(const float4*)&x[(size_t)s0 * 128 + lane * 4];
        acc.x += x0.x * d0; acc.y += x0.y * d0;
        acc.z += x0.z * d0; acc.w += x0.w * d0;
    }

    acc.x *= dself; acc.y *= dself; acc.z *= dself; acc.w *= dself;
    uint32_t h01, l01, h23, l23;
    bf16_split2(acc.x, acc.y, h01, l01);
    bf16_split2(acc.z, acc.w, h23, l23);
    size_t o = (size_t)node * 128 + lane * 4;
    *(uint32_t*)&g_a0_hi[o]     = h01;
    *(uint32_t*)&g_a0_hi[o + 2] = h23;
    *(uint32_t*)&g_a0_lo[o]     = l01;
    *(uint32_t*)&g_a0_lo[o + 2] = l23;
}

// ---------------- layer-2 aggregation + fused layer-3 GEMM (2-wide) ----------------
__global__ __launch_bounds__(256) void k_agg_out(const float* __restrict__ b2,
                                                 const float* __restrict__ W3) {
    __shared__ float w3s[256];
    if (threadIdx.x < 256) w3s[threadIdx.x] = W3[threadIdx.x];
    __syncthreads();

    int node = (blockIdx.x * blockDim.x + threadIdx.x) >> 5;
    int lane = threadIdx.x & 31;
    if (node >= N_NODES) return;

    float4 acc = *(const float4*)&g_hs2[(size_t)node * 128 + lane * 4];
    int e = g_rowptr[node], eEnd = g_rowptr[node + 1];
    for (; e + 1 < eEnd; e += 2) {
        int s0 = g_col[e], s1 = g_col[e + 1];
        float4 x0 = *(const float4*)&g_hs2[(size_t)s0 * 128 + lane * 4];
        float4 x1 = *(const float4*)&g_hs2[(size_t)s1 * 128 + lane * 4];
        acc.x += x0.x + x1.x;
        acc.y += x0.y + x1.y;
        acc.z += x0.z + x1.z;
        acc.w += x0.w + x1.w;
    }
    if (e < eEnd) {
        int s0 = g_col[e];
        float4 x0 = *(const float4*)&g_hs2[(size_t)s0 * 128 + lane * 4];
        acc.x += x0.x; acc.y += x0.y; acc.z += x0.z; acc.w += x0.w;
    }

    float d = g_dinv[node];
    float4 b = *(const float4*)&b2[lane * 4];
    float o0 = fmaxf(acc.x * d + b.x, 0.f);
    float o1 = fmaxf(acc.y * d + b.y, 0.f);
    float o2 = fmaxf(acc.z * d + b.z, 0.f);
    float o3 = fmaxf(acc.w * d + b.w, 0.f);

    int c = lane * 4;
    float p0 = o0 * w3s[c * 2 + 0] + o1 * w3s[(c + 1) * 2 + 0]
             + o2 * w3s[(c + 2) * 2 + 0] + o3 * w3s[(c + 3) * 2 + 0];
    float p1 = o0 * w3s[c * 2 + 1] + o1 * w3s[(c + 1) * 2 + 1]
             + o2 * w3s[(c + 2) * 2 + 1] + o3 * w3s[(c + 3) * 2 + 1];
    #pragma unroll
    for (int off = 16; off; off >>= 1) {
        p0 += __shfl_down_sync(0xFFFFFFFFu, p0, off);
        p1 += __shfl_down_sync(0xFFFFFFFFu, p1, off);
    }
    if (lane == 0) {
        g_hs3[(size_t)node * 2 + 0] = p0 * d;
        g_hs3[(size_t)node * 2 + 1] = p1 * d;
    }
}

// ---------------- final aggregation + log_softmax + deferred state reset ----------------
__global__ __launch_bounds__(256) void k_agg3(const float* __restrict__ b3,
                                              float* __restrict__ out) {
    int i = blockIdx.x * blockDim.x + threadIdx.x;
    if (i >= N_NODES) return;
    float2 acc = *(const float2*)&g_hs3[(size_t)i * 2];
    int e = g_rowptr[i], eE = g_rowptr[i + 1];
    for (; e < eE; e++) {
        int s = g_col[e];
        float2 x = *(const float2*)&g_hs3[(size_t)s * 2];
        acc.x += x.x;
        acc.y += x.y;
    }
    float d = g_dinv[i];
    float v0 = acc.x * d + b3[0];
    float v1 = acc.y * d + b3[1];
    float m = fmaxf(v0, v1);
    float lse = m + logf(expf(v0 - m) + expf(v1 - m));
    out[(size_t)i * 2 + 0] = v0 - lse;
    out[(size_t)i * 2 + 1] = v1 - lse;

    // zero counts for the next call (first call sees static zero-init)
    g_counts[i] = 0;
}

// ---------------- launch ----------------
extern "C" void kernel_launch(void* const* d_in, const int* in_sizes, int n_in,
                              void* d_out, int out_size) {
    const float* x  = (const float*)d_in[0];
    const float* W1 = (const float*)d_in[1];
    const float* b1 = (const float*)d_in[2];
    const float* W2 = (const float*)d_in[3];
    const float* b2 = (const float*)d_in[4];
    const float* W3 = (const float*)d_in[5];
    const float* b3 = (const float*)d_in[6];
    const int* ei   = (const int*)d_in[7];   // int32 (JAX x64 disabled)
    const int* src  = ei;
    const int* dst  = ei + N_EDGES;
    float* out = (float*)d_out;

    __nv_bfloat16 *a0hi, *a0lo, *wt1hi, *wt1lo, *wt2hi, *wt2lo;
    float* hs2;
    cudaGetSymbolAddress((void**)&a0hi, g_a0_hi);
    cudaGetSymbolAddress((void**)&a0lo, g_a0_lo);
    cudaGetSymbolAddress((void**)&wt1hi, g_wt1_hi);
    cudaGetSymbolAddress((void**)&wt1lo, g_wt1_lo);
    cudaGetSymbolAddress((void**)&wt2hi, g_wt2_hi);
    cudaGetSymbolAddress((void**)&wt2lo, g_wt2_lo);
    cudaGetSymbolAddress((void**)&hs2, g_hs2);

    const int smemBytes = SMEM_U32 * 4;   // 229376 B (< 232448 opt-in cap)
    cudaFuncSetAttribute(k_gemm12, cudaFuncAttributeMaxDynamicSharedMemorySize, smemBytes);

    const int TB = 256;
    int edgeBlocks4 = (N_EDGES / 4 + TB - 1) / TB;
    int aggBlocks = (N_NODES * 32 + TB - 1) / TB;

    // 1: degree count (int4, MLP=4) + fused W1/W2 split
    k_count<<<edgeBlocks4, TB>>>(dst, W1, W2);
    // 2-4: three-phase scan + dinv + cursor
    k_scan1<<<SCAN_BLKS, TB>>>();
    k_scan2<<<1, TB>>>();
    k_scan3<<<SCAN_BLKS, TB>>>();
    // 5: CSR fill (int4, MLP=4)
    k_fill<<<edgeBlocks4, TB>>>(src, dst);
    // 6: ax -> split planes [N,128]
    k_agg0<<<aggBlocks, TB>>>(x);
    // 7: h1 = relu(ax@W1+b1); hs2 = dinv*(h1@W2)  (fused, h1 stays in SMEM)
    k_gemm12<<<N_PAD / 128, TB, smemBytes>>>(a0hi, a0lo, wt1hi, wt1lo, wt2hi, wt2lo, b1, hs2);
    // 8: h2 = relu(dinv*(agg hs2)+b2); hs3 = dinv*(h2@W3)
    k_agg_out<<<aggBlocks, TB>>>(b2, W3);
    // 9: out = log_softmax; deferred counts reset
    k_agg3<<<SCAN_BLKS, TB>>>(b3, out);
}

// round 14
// speedup vs baseline: 1.4440x; 1.4440x over previous
#include <cuda_runtime.h>
#include <cuda_bf16.h>
#include <math.h>
#include <stdint.h>

#define N_NODES 50000
#define N_EDGES 600000
#define N_PAD   50048   // 391*128
#define IN_CH   128
#define HID1    256
#define HID2    128
#define SCAN_BLKS 196   // ceil(50000/256)

// ---------------- device scratch ----------------
__device__ int   g_counts[N_NODES];
__device__ int   g_rowptr[N_NODES + 1];
__device__ int   g_cursor[N_NODES];
__device__ float g_dinv[N_NODES];
__device__ int   g_col[N_EDGES];
__device__ int   g_bsum[SCAN_BLKS];
__device__ int   g_boff[SCAN_BLKS];

__device__ __align__(16) __nv_bfloat16 g_a0_hi[(size_t)N_PAD * 128];
__device__ __align__(16) __nv_bfloat16 g_a0_lo[(size_t)N_PAD * 128];
__device__ __align__(16) __nv_bfloat16 g_wt1_hi[256 * 128];
__device__ __align__(16) __nv_bfloat16 g_wt1_lo[256 * 128];
__device__ __align__(16) __nv_bfloat16 g_wt2_hi[128 * 256];
__device__ __align__(16) __nv_bfloat16 g_wt2_lo[128 * 256];
__device__ float g_hs2[(size_t)N_NODES * 128];
__device__ float g_hs3[(size_t)N_NODES * 2];

// ---------------- prep: split+transpose W1/W2, zero counts ----------------
__global__ __launch_bounds__(256) void k_prep(const float* __restrict__ W1,
                                              const float* __restrict__ W2) {
    int idx = blockIdx.x * 256 + threadIdx.x;   // 0 .. 65535
    if (idx < 128 * 256) {
        int k = idx >> 8, m = idx & 255;          // W1[k][m], K=128, M=256
        float v = W1[idx];
        __nv_bfloat16 h = __float2bfloat16_rn(v);
        __nv_bfloat16 l = __float2bfloat16_rn(v - __bfloat162float(h));
        g_wt1_hi[m * 128 + k] = h;
        g_wt1_lo[m * 128 + k] = l;
    } else {
        int j = idx - 128 * 256;
        int k = j >> 7, m = j & 127;              // W2[k][m], K=256, M=128
        float v = W2[j];
        __nv_bfloat16 h = __float2bfloat16_rn(v);
        __nv_bfloat16 l = __float2bfloat16_rn(v - __bfloat162float(h));
        g_wt2_hi[m * 256 + k] = h;
        g_wt2_lo[m * 256 + k] = l;
    }
    if (idx < N_NODES) g_counts[idx] = 0;
}

// ---------------- degree count, 4 edges/thread (MLP=4) ----------------
__global__ void k_count(const int* __restrict__ dst) {
    int t = blockIdx.x * blockDim.x + threadIdx.x;
    if (t * 4 >= N_EDGES) return;
    int4 d4 = *(const int4*)&dst[t * 4];
    atomicAdd(&g_counts[d4.x], 1);
    atomicAdd(&g_counts[d4.y], 1);
    atomicAdd(&g_counts[d4.z], 1);
    atomicAdd(&g_counts[d4.w], 1);
}

// ---------------- 3-phase scan ----------------
__global__ __launch_bounds__(256) void k_scan1() {
    __shared__ int sh[256];
    int b = blockIdx.x, t = threadIdx.x;
    int i = b * 256 + t;
    int v = (i < N_NODES) ? g_counts[i] : 0;
    sh[t] = v;
    __syncthreads();
    #pragma unroll
    for (int off = 1; off < 256; off <<= 1) {
        int u = (t >= off) ? sh[t - off] : 0;
        __syncthreads();
        sh[t] += u;
        __syncthreads();
    }
    if (i < N_NODES) g_rowptr[i + 1] = sh[t];
    if (t == 255) g_bsum[b] = sh[255];
}

__global__ __launch_bounds__(256) void k_scan2() {
    __shared__ int sh[256];
    int t = threadIdx.x;
    int v = (t < SCAN_BLKS) ? g_bsum[t] : 0;
    sh[t] = v;
    __syncthreads();
    #pragma unroll
    for (int off = 1; off < 256; off <<= 1) {
        int u = (t >= off) ? sh[t - off] : 0;
        __syncthreads();
        sh[t] += u;
        __syncthreads();
    }
    if (t < SCAN_BLKS) g_boff[t] = sh[t] - v;  // exclusive
}

__global__ __launch_bounds__(256) void k_scan3() {
    int b = blockIdx.x, t = threadIdx.x;
    int i = b * 256 + t;
    if (i < N_NODES) {
        int rp1 = g_rowptr[i + 1] + g_boff[b];
        g_rowptr[i + 1] = rp1;
        int c = g_counts[i];
        g_cursor[i] = rp1 - c;
        g_dinv[i] = rsqrtf((float)(c + 1));
    }
    if (i == 0) g_rowptr[0] = 0;
}

// ---------------- CSR fill, 4 edges/thread (MLP=4 atomics) ----------------
__global__ void k_fill(const int* __restrict__ src,
                       const int* __restrict__ dst) {
    int t = blockIdx.x * blockDim.x + threadIdx.x;
    if (t * 4 >= N_EDGES) return;
    int4 s4 = *(const int4*)&src[t * 4];
    int4 d4 = *(const int4*)&dst[t * 4];
    int p0 = atomicAdd(&g_cursor[d4.x], 1);
    int p1 = atomicAdd(&g_cursor[d4.y], 1);
    int p2 = atomicAdd(&g_cursor[d4.z], 1);
    int p3 = atomicAdd(&g_cursor[d4.w], 1);
    g_col[p0] = s4.x;
    g_col[p1] = s4.y;
    g_col[p2] = s4.z;
    g_col[p3] = s4.w;
}

// ---------------- helpers ----------------
__device__ __forceinline__ void bf16_split2(float a, float b, uint32_t& hi, uint32_t& lo) {
    __nv_bfloat162 h = __floats2bfloat162_rn(a, b);
    hi = *(uint32_t*)&h;
    float ra = a - __bfloat162float(h.x);
    float rb = b - __bfloat162float(h.y);
    __nv_bfloat162 l = __floats2bfloat162_rn(ra, rb);
    lo = *(uint32_t*)&l;
}

__device__ __forceinline__ void mma_bf16(float* c, uint32_t a0, uint32_t a1,
                                         uint32_t a2, uint32_t a3,
                                         uint32_t b0, uint32_t b1) {
    asm volatile(
        "mma.sync.aligned.m16n8k16.row.col.f32.bf16.bf16.f32 "
        "{%0,%1,%2,%3}, {%4,%5,%6,%7}, {%8,%9}, {%0,%1,%2,%3};"
        : "+f"(c[0]), "+f"(c[1]), "+f"(c[2]), "+f"(c[3])
        : "r"(a0), "r"(a1), "r"(a2), "r"(a3), "r"(b0), "r"(b1));
}

__device__ __forceinline__ void cp16(uint32_t saddr, const void* gptr) {
    asm volatile("cp.async.ca.shared.global [%0], [%1], 16;" :: "r"(saddr), "l"(gptr));
}

// ---------------- fused GEMM1+GEMM2 (3xBF16 mma.sync, pipelined) ----------------
#define AS2 68
#define HS2 132
#define OFF_AL   (128 * AS2)
#define OFF_H1H  (2 * 128 * AS2)
#define OFF_H1L  (OFF_H1H + 128 * HS2)
#define OFF_STG  (OFF_H1L + 128 * HS2)
#define STG_SZ   (2 * 128 * 12)
#define SMEM_U32 (OFF_STG + 2 * STG_SZ)

__global__ __launch_bounds__(256) void k_gemm12(const __nv_bfloat16* __restrict__ a_hi,
                                                const __nv_bfloat16* __restrict__ a_lo,
                                                const __nv_bfloat16* __restrict__ w1h,
                                                const __nv_bfloat16* __restrict__ w1l,
                                                const __nv_bfloat16* __restrict__ w2h,
                                                const __nv_bfloat16* __restrict__ w2l,
                                                const float* __restrict__ b1,
                                                float* __restrict__ hs2) {
    extern __shared__ __align__(16) uint32_t sm[];

    const int tid  = threadIdx.x;
    const int lane = tid & 31;
    const int warp = tid >> 5;
    const int gid  = lane >> 2;
    const int tig  = lane & 3;
    const int warpM = warp & 3;
    const int warpN = warp >> 2;
    const int rowBase = blockIdx.x * 128;

    const uint32_t sb = (uint32_t)__cvta_generic_to_shared(sm);

    for (int u = tid; u < 4096; u += 256) {
        int p = u >> 11;
        int v = u & 2047;
        int r = v >> 4, ch = v & 15;
        const __nv_bfloat16* g = (p ? a_lo : a_hi) + (size_t)(rowBase + r) * 128 + ch * 8;
        uint32_t d = sb + (uint32_t)(((p ? OFF_AL : 0) + r * AS2 + ch * 4) << 2);
        cp16(d, g);
    }

    auto loadB = [&](int s, const __nv_bfloat16* bh, const __nv_bfloat16* bl,
                     int mBase, int Kb, int kBase) {
        int r = tid >> 1, ch = tid & 1;
        size_t go = (size_t)(mBase + r) * Kb + kBase + ch * 8;
        uint32_t d = sb + (uint32_t)((OFF_STG + s * STG_SZ + r * 12 + ch * 4) << 2);
        cp16(d, bh + go);
        cp16(d + (uint32_t)((128 * 12) << 2), bl + go);
    };

    float acc[2][8][4];

    // =================== phase 1: two column blocks of h1 ===================
    #pragma unroll 1
    for (int cb = 0; cb < 2; cb++) {
        #pragma unroll
        for (int mt = 0; mt < 2; mt++)
            #pragma unroll
            for (int nt = 0; nt < 8; nt++)
                #pragma unroll
                for (int j = 0; j < 4; j++) acc[mt][nt][j] = 0.f;

        loadB(0, w1h, w1l, cb * 128, 128, 0);
        asm volatile("cp.async.commit_group;");

        #pragma unroll 1
        for (int i = 0; i < 8; i++) {
            if (i < 7) {
                loadB((i + 1) & 1, w1h, w1l, cb * 128, 128, (i + 1) * 16);
                asm volatile("cp.async.commit_group;");
                asm volatile("cp.async.wait_group 1;");
            } else {
                asm volatile("cp.async.wait_group 0;");
            }
            __syncthreads();

            const uint32_t* Bh = &sm[OFF_STG + (i & 1) * STG_SZ];
            const uint32_t* Bl = Bh + 128 * 12;
            const int ks = i * 8;

            uint32_t ahi[2][4], alo[2][4];
            #pragma unroll
            for (int mt = 0; mt < 2; mt++) {
                int r0 = warpM * 32 + mt * 16 + gid;
                ahi[mt][0] = sm[r0 * AS2 + ks + tig];
                ahi[mt][1] = sm[(r0 + 8) * AS2 + ks + tig];
                ahi[mt][2] = sm[r0 * AS2 + ks + tig + 4];
                ahi[mt][3] = sm[(r0 + 8) * AS2 + ks + tig + 4];
                alo[mt][0] = sm[OFF_AL + r0 * AS2 + ks + tig];
                alo[mt][1] = sm[OFF_AL + (r0 + 8) * AS2 + ks + tig];
                alo[mt][2] = sm[OFF_AL + r0 * AS2 + ks + tig + 4];
                alo[mt][3] = sm[OFF_AL + (r0 + 8) * AS2 + ks + tig + 4];
            }
            #pragma unroll
            for (int nt = 0; nt < 8; nt++) {
                int c0 = warpN * 64 + nt * 8 + gid;
                uint32_t bh0 = Bh[c0 * 12 + tig], bh1 = Bh[c0 * 12 + tig + 4];
                uint32_t bl0 = Bl[c0 * 12 + tig], bl1 = Bl[c0 * 12 + tig + 4];
                #pragma unroll
                for (int mt = 0; mt < 2; mt++) {
                    mma_bf16(acc[mt][nt], ahi[mt][0], ahi[mt][1], ahi[mt][2], ahi[mt][3], bh0, bh1);
                    mma_bf16(acc[mt][nt], ahi[mt][0], ahi[mt][1], ahi[mt][2], ahi[mt][3], bl0, bl1);
                    mma_bf16(acc[mt][nt], alo[mt][0], alo[mt][1], alo[mt][2], alo[mt][3], bh0, bh1);
                }
            }
            __syncthreads();
        }

        // epilogue: relu + bias, split into H1 planes
        #pragma unroll
        for (int mt = 0; mt < 2; mt++) {
            int rl = warpM * 32 + mt * 16 + gid;
            #pragma unroll
            for (int nt = 0; nt < 8; nt++) {
                int col = cb * 128 + warpN * 64 + nt * 8 + 2 * tig;
                int cidx = col >> 1;
                float bb0 = b1[col], bb1 = b1[col + 1];
                float* c = acc[mt][nt];
                uint32_t h, l;
                float v0 = fmaxf(c[0] + bb0, 0.f), v1 = fmaxf(c[1] + bb1, 0.f);
                bf16_split2(v0, v1, h, l);
                sm[OFF_H1H + rl * HS2 + cidx] = h;
                sm[OFF_H1L + rl * HS2 + cidx] = l;
                v0 = fmaxf(c[2] + bb0, 0.f); v1 = fmaxf(c[3] + bb1, 0.f);
                bf16_split2(v0, v1, h, l);
                sm[OFF_H1H + (rl + 8) * HS2 + cidx] = h;
                sm[OFF_H1L + (rl + 8) * HS2 + cidx] = l;
            }
        }
    }

    // =================== phase 2: hs2 = dinv * (h1 @ W2) ===================
    #pragma unroll
    for (int mt = 0; mt < 2; mt++)
        #pragma unroll
        for (int nt = 0; nt < 8; nt++)
            #pragma unroll
            for (int j = 0; j < 4; j++) acc[mt][nt][j] = 0.f;

    loadB(0, w2h, w2l, 0, 256, 0);
    asm volatile("cp.async.commit_group;");

    #pragma unroll 1
    for (int i = 0; i < 16; i++) {
        if (i < 15) {
            loadB((i + 1) & 1, w2h, w2l, 0, 256, (i + 1) * 16);
            asm volatile("cp.async.commit_group;");
            asm volatile("cp.async.wait_group 1;");
        } else {
            asm volatile("cp.async.wait_group 0;");
        }
        __syncthreads();   // also orders H1 writes before first reads

        const uint32_t* Bh = &sm[OFF_STG + (i & 1) * STG_SZ];
        const uint32_t* Bl = Bh + 128 * 12;
        const int ks = i * 8;

        uint32_t ahi[2][4], alo[2][4];
        #pragma unroll
        for (int mt = 0; mt < 2; mt++) {
            int r0 = warpM * 32 + mt * 16 + gid;
            ahi[mt][0] = sm[OFF_H1H + r0 * HS2 + ks + tig];
            ahi[mt][1] = sm[OFF_H1H + (r0 + 8) * HS2 + ks + tig];
            ahi[mt][2] = sm[OFF_H1H + r0 * HS2 + ks + tig + 4];
            ahi[mt][3] = sm[OFF_H1H + (r0 + 8) * HS2 + ks + tig + 4];
            alo[mt][0] = sm[OFF_H1L + r0 * HS2 + ks + tig];
            alo[mt][1] = sm[OFF_H1L + (r0 + 8) * HS2 + ks + tig];
            alo[mt][2] = sm[OFF_H1L + r0 * HS2 + ks + tig + 4];
            alo[mt][3] = sm[OFF_H1L + (r0 + 8) * HS2 + ks + tig + 4];
        }
        #pragma unroll
        for (int nt = 0; nt < 8; nt++) {
            int c0 = warpN * 64 + nt * 8 + gid;
            uint32_t bh0 = Bh[c0 * 12 + tig], bh1 = Bh[c0 * 12 + tig + 4];
            uint32_t bl0 = Bl[c0 * 12 + tig], bl1 = Bl[c0 * 12 + tig + 4];
            #pragma unroll
            for (int mt = 0; mt < 2; mt++) {
                mma_bf16(acc[mt][nt], ahi[mt][0], ahi[mt][1], ahi[mt][2], ahi[mt][3], bh0, bh1);
                mma_bf16(acc[mt][nt], ahi[mt][0], ahi[mt][1], ahi[mt][2], ahi[mt][3], bl0, bl1);
                mma_bf16(acc[mt][nt], alo[mt][0], alo[mt][1], alo[mt][2], alo[mt][3], bh0, bh1);
            }
        }
        __syncthreads();
    }

    // epilogue: dinv scale -> global
    #pragma unroll
    for (int mt = 0; mt < 2; mt++) {
        int r0 = rowBase + warpM * 32 + mt * 16 + gid;
        #pragma unroll
        for (int nt = 0; nt < 8; nt++) {
            int col = warpN * 64 + nt * 8 + 2 * tig;
            float* c = acc[mt][nt];
            if (r0 < N_NODES) {
                float d = g_dinv[r0];
                *(float2*)&hs2[(size_t)r0 * 128 + col] = make_float2(c[0] * d, c[1] * d);
            }
            if (r0 + 8 < N_NODES) {
                float d = g_dinv[r0 + 8];
                *(float2*)&hs2[(size_t)(r0 + 8) * 128 + col] = make_float2(c[2] * d, c[3] * d);
            }
        }
    }
}

// ---------------- layer-0 aggregation -> split bf16 planes (2-wide) ----------------
__global__ __launch_bounds__(256) void k_agg0(const float* __restrict__ x) {
    int node = (blockIdx.x * blockDim.x + threadIdx.x) >> 5;
    int lane = threadIdx.x & 31;
    if (node >= N_NODES) return;

    float dself = g_dinv[node];
    float4 acc = *(const float4*)&x[(size_t)node * 128 + lane * 4];
    acc.x *= dself; acc.y *= dself; acc.z *= dself; acc.w *= dself;

    int e = g_rowptr[node], eEnd = g_rowptr[node + 1];
    for (; e + 1 < eEnd; e += 2) {
        int s0 = g_col[e], s1 = g_col[e + 1];
        float d0 = g_dinv[s0], d1 = g_dinv[s1];
        float4 x0 = *(const float4*)&x[(size_t)s0 * 128 + lane * 4];
        float4 x1 = *(const float4*)&x[(size_t)s1 * 128 + lane * 4];
        acc.x += x0.x * d0 + x1.x * d1;
        acc.y += x0.y * d0 + x1.y * d1;
        acc.z += x0.z * d0 + x1.z * d1;
        acc.w += x0.w * d0 + x1.w * d1;
    }
    if (e < eEnd) {
        int s0 = g_col[e];
        float d0 = g_dinv[s0];
        float4 x0 = *(const float4*)&x[(size_t)s0 * 128 + lane * 4];
        acc.x += x0.x * d0; acc.y += x0.y * d0;
        acc.z += x0.z * d0; acc.w += x0.w * d0;
    }

    acc.x *= dself; acc.y *= dself; acc.z *= dself; acc.w *= dself;
    uint32_t h01, l01, h23, l23;
    bf16_split2(acc.x, acc.y, h01, l01);
    bf16_split2(acc.z, acc.w, h23, l23);
    size_t o = (size_t)node * 128 + lane * 4;
    *(uint32_t*)&g_a0_hi[o]     = h01;
    *(uint32_t*)&g_a0_hi[o + 2] = h23;
    *(uint32_t*)&g_a0_lo[o]     = l01;
    *(uint32_t*)&g_a0_lo[o + 2] = l23;
}

// ---------------- layer-2 aggregation + fused layer-3 GEMM (2-wide) ----------------
__global__ __launch_bounds__(256) void k_agg_out(const float* __restrict__ b2,
                                                 const float* __restrict__ W3) {
    __shared__ float w3s[256];
    if (threadIdx.x < 256) w3s[threadIdx.x] = W3[threadIdx.x];
    __syncthreads();

    int node = (blockIdx.x * blockDim.x + threadIdx.x) >> 5;
    int lane = threadIdx.x & 31;
    if (node >= N_NODES) return;

    float4 acc = *(const float4*)&g_hs2[(size_t)node * 128 + lane * 4];
    int e = g_rowptr[node], eEnd = g_rowptr[node + 1];
    for (; e + 1 < eEnd; e += 2) {
        int s0 = g_col[e], s1 = g_col[e + 1];
        float4 x0 = *(const float4*)&g_hs2[(size_t)s0 * 128 + lane * 4];
        float4 x1 = *(const float4*)&g_hs2[(size_t)s1 * 128 + lane * 4];
        acc.x += x0.x + x1.x;
        acc.y += x0.y + x1.y;
        acc.z += x0.z + x1.z;
        acc.w += x0.w + x1.w;
    }
    if (e < eEnd) {
        int s0 = g_col[e];
        float4 x0 = *(const float4*)&g_hs2[(size_t)s0 * 128 + lane * 4];
        acc.x += x0.x; acc.y += x0.y; acc.z += x0.z; acc.w += x0.w;
    }

    float d = g_dinv[node];
    float4 b = *(const float4*)&b2[lane * 4];
    float o0 = fmaxf(acc.x * d + b.x, 0.f);
    float o1 = fmaxf(acc.y * d + b.y, 0.f);
    float o2 = fmaxf(acc.z * d + b.z, 0.f);
    float o3 = fmaxf(acc.w * d + b.w, 0.f);

    int c = lane * 4;
    float p0 = o0 * w3s[c * 2 + 0] + o1 * w3s[(c + 1) * 2 + 0]
             + o2 * w3s[(c + 2) * 2 + 0] + o3 * w3s[(c + 3) * 2 + 0];
    float p1 = o0 * w3s[c * 2 + 1] + o1 * w3s[(c + 1) * 2 + 1]
             + o2 * w3s[(c + 2) * 2 + 1] + o3 * w3s[(c + 3) * 2 + 1];
    #pragma unroll
    for (int off = 16; off; off >>= 1) {
        p0 += __shfl_down_sync(0xFFFFFFFFu, p0, off);
        p1 += __shfl_down_sync(0xFFFFFFFFu, p1, off);
    }
    if (lane == 0) {
        g_hs3[(size_t)node * 2 + 0] = p0 * d;
        g_hs3[(size_t)node * 2 + 1] = p1 * d;
    }
}

// ---------------- final aggregation + log_softmax (CH=2) ----------------
__global__ __launch_bounds__(256) void k_agg3(const float* __restrict__ b3,
                                              float* __restrict__ out) {
    int i = blockIdx.x * blockDim.x + threadIdx.x;
    if (i >= N_NODES) return;
    float2 acc = *(const float2*)&g_hs3[(size_t)i * 2];
    int e = g_rowptr[i], eE = g_rowptr[i + 1];
    for (; e < eE; e++) {
        int s = g_col[e];
        float2 x = *(const float2*)&g_hs3[(size_t)s * 2];
        acc.x += x.x;
        acc.y += x.y;
    }
    float d = g_dinv[i];
    float v0 = acc.x * d + b3[0];
    float v1 = acc.y * d + b3[1];
    float m = fmaxf(v0, v1);
    float lse = m + logf(expf(v0 - m) + expf(v1 - m));
    out[(size_t)i * 2 + 0] = v0 - lse;
    out[(size_t)i * 2 + 1] = v1 - lse;
}

// ---------------- launch ----------------
extern "C" void kernel_launch(void* const* d_in, const int* in_sizes, int n_in,
                              void* d_out, int out_size) {
    const float* x  = (const float*)d_in[0];
    const float* W1 = (const float*)d_in[1];
    const float* b1 = (const float*)d_in[2];
    const float* W2 = (const float*)d_in[3];
    const float* b2 = (const float*)d_in[4];
    const float* W3 = (const float*)d_in[5];
    const float* b3 = (const float*)d_in[6];
    const int* ei   = (const int*)d_in[7];   // int32 (JAX x64 disabled)
    const int* src  = ei;
    const int* dst  = ei + N_EDGES;
    float* out = (float*)d_out;

    __nv_bfloat16 *a0hi, *a0lo, *wt1hi, *wt1lo, *wt2hi, *wt2lo;
    float* hs2;
    cudaGetSymbolAddress((void**)&a0hi, g_a0_hi);
    cudaGetSymbolAddress((void**)&a0lo, g_a0_lo);
    cudaGetSymbolAddress((void**)&wt1hi, g_wt1_hi);
    cudaGetSymbolAddress((void**)&wt1lo, g_wt1_lo);
    cudaGetSymbolAddress((void**)&wt2hi, g_wt2_hi);
    cudaGetSymbolAddress((void**)&wt2lo, g_wt2_lo);
    cudaGetSymbolAddress((void**)&hs2, g_hs2);

    const int smemBytes = SMEM_U32 * 4;   // 229376 B (< 232448 opt-in cap)
    cudaFuncSetAttribute(k_gemm12, cudaFuncAttributeMaxDynamicSharedMemorySize, smemBytes);

    const int TB = 256;
    int edgeBlocks4 = (N_EDGES / 4 + TB - 1) / TB;
    int aggBlocks = (N_NODES * 32 + TB - 1) / TB;

    // 1: weight split + zero counts
    k_prep<<<256, TB>>>(W1, W2);
    // 2: degree count (int4, MLP=4)
    k_count<<<edgeBlocks4, TB>>>(dst);
    // 3-5: three-phase scan + dinv + cursor
    k_scan1<<<SCAN_BLKS, TB>>>();
    k_scan2<<<1, TB>>>();
    k_scan3<<<SCAN_BLKS, TB>>>();
    // 6: CSR fill (int4, MLP=4)
    k_fill<<<edgeBlocks4, TB>>>(src, dst);
    // 7: ax -> split planes [N,128]
    k_agg0<<<aggBlocks, TB>>>(x);
    // 8: h1 = relu(ax@W1+b1); hs2 = dinv*(h1@W2)  (fused, h1 stays in SMEM)
    k_gemm12<<<N_PAD / 128, TB, smemBytes>>>(a0hi, a0lo, wt1hi, wt1lo, wt2hi, wt2lo, b1, hs2);
    // 9: h2 = relu(dinv*(agg hs2)+b2); hs3 = dinv*(h2@W3)
    k_agg_out<<<aggBlocks, TB>>>(b2, W3);
    // 10: out = log_softmax
    k_agg3<<<SCAN_BLKS, TB>>>(b3, out);
}

// round 15
// speedup vs baseline: 1.4453x; 1.0009x over previous
#include <cuda_runtime.h>
#include <cuda_bf16.h>
#include <math.h>
#include <stdint.h>

#define N_NODES 50000
#define N_EDGES 600000
#define N_PAD   50048   // 391*128
#define IN_CH   128
#define HID1    256
#define HID2    128
#define SCAN_BLKS 196   // ceil(50000/256)

// ---------------- device scratch ----------------
__device__ int   g_counts[N_NODES];
__device__ int   g_rowptr[N_NODES + 1];
__device__ int   g_cursor[N_NODES];
__device__ float g_dinv[N_NODES];
__device__ int   g_col[N_EDGES];
__device__ int   g_bsum[SCAN_BLKS];

__device__ __align__(16) __nv_bfloat16 g_a0_hi[(size_t)N_PAD * 128];
__device__ __align__(16) __nv_bfloat16 g_a0_lo[(size_t)N_PAD * 128];
__device__ __align__(16) __nv_bfloat16 g_wt1_hi[256 * 128];
__device__ __align__(16) __nv_bfloat16 g_wt1_lo[256 * 128];
__device__ __align__(16) __nv_bfloat16 g_wt2_hi[128 * 256];
__device__ __align__(16) __nv_bfloat16 g_wt2_lo[128 * 256];
__device__ float g_hs2[(size_t)N_NODES * 128];
__device__ float g_hs3[(size_t)N_NODES * 2];

// ---------------- prep: split+transpose W1/W2, zero counts ----------------
__global__ __launch_bounds__(256) void k_prep(const float* __restrict__ W1,
                                              const float* __restrict__ W2) {
    int idx = blockIdx.x * 256 + threadIdx.x;   // 0 .. 65535
    if (idx < 128 * 256) {
        int k = idx >> 8, m = idx & 255;          // W1[k][m], K=128, M=256
        float v = W1[idx];
        __nv_bfloat16 h = __float2bfloat16_rn(v);
        __nv_bfloat16 l = __float2bfloat16_rn(v - __bfloat162float(h));
        g_wt1_hi[m * 128 + k] = h;
        g_wt1_lo[m * 128 + k] = l;
    } else {
        int j = idx - 128 * 256;
        int k = j >> 7, m = j & 127;              // W2[k][m], K=256, M=128
        float v = W2[j];
        __nv_bfloat16 h = __float2bfloat16_rn(v);
        __nv_bfloat16 l = __float2bfloat16_rn(v - __bfloat162float(h));
        g_wt2_hi[m * 256 + k] = h;
        g_wt2_lo[m * 256 + k] = l;
    }
    if (idx < N_NODES) g_counts[idx] = 0;
}

// ---------------- degree count, 4 edges/thread (MLP=4) ----------------
__global__ void k_count(const int* __restrict__ dst) {
    int t = blockIdx.x * blockDim.x + threadIdx.x;
    if (t * 4 >= N_EDGES) return;
    int4 d4 = *(const int4*)&dst[t * 4];
    atomicAdd(&g_counts[d4.x], 1);
    atomicAdd(&g_counts[d4.y], 1);
    atomicAdd(&g_counts[d4.z], 1);
    atomicAdd(&g_counts[d4.w], 1);
}

// ---------------- scan phase 1: per-block inclusive scan + block sums ----------------
__global__ __launch_bounds__(256) void k_scan1() {
    __shared__ int sh[256];
    int b = blockIdx.x, t = threadIdx.x;
    int i = b * 256 + t;
    int v = (i < N_NODES) ? g_counts[i] : 0;
    sh[t] = v;
    __syncthreads();
    #pragma unroll
    for (int off = 1; off < 256; off <<= 1) {
        int u = (t >= off) ? sh[t - off] : 0;
        __syncthreads();
        sh[t] += u;
        __syncthreads();
    }
    if (i < N_NODES) g_rowptr[i + 1] = sh[t];
    if (t == 255) g_bsum[b] = sh[255];
}

// ---------------- scan phase 2 (fused): per-block predecessor reduction + apply ----------------
// Block b computes prev = sum(bsum[0..b-1]) itself (196 < 256, one masked load +
// block reduction), then applies offsets and computes dinv/cursor. Replaces the
// old single-block k_scan2 launch.
__global__ __launch_bounds__(256) void k_scan3() {
    __shared__ int sh[8];
    __shared__ int s_prev;
    int b = blockIdx.x, t = threadIdx.x;

    int v = (t < b) ? g_bsum[t] : 0;   // b <= 195 < 256: single pass covers all preds
    #pragma unroll
    for (int o = 16; o; o >>= 1) v += __shfl_down_sync(0xFFFFFFFFu, v, o);
    if ((t & 31) == 0) sh[t >> 5] = v;
    __syncthreads();
    if (t < 8) {
        int w = sh[t];
        #pragma unroll
        for (int o = 4; o; o >>= 1) w += __shfl_down_sync(0x000000FFu, w, o);
        if (t == 0) s_prev = w;
    }
    __syncthreads();
    int prev = s_prev;

    int i = b * 256 + t;
    if (i < N_NODES) {
        int rp1 = g_rowptr[i + 1] + prev;
        g_rowptr[i + 1] = rp1;
        int c = g_counts[i];
        g_cursor[i] = rp1 - c;
        g_dinv[i] = rsqrtf((float)(c + 1));
    }
    if (i == 0) g_rowptr[0] = 0;
}

// ---------------- CSR fill, 4 edges/thread (MLP=4 atomics) ----------------
__global__ void k_fill(const int* __restrict__ src,
                       const int* __restrict__ dst) {
    int t = blockIdx.x * blockDim.x + threadIdx.x;
    if (t * 4 >= N_EDGES) return;
    int4 s4 = *(const int4*)&src[t * 4];
    int4 d4 = *(const int4*)&dst[t * 4];
    int p0 = atomicAdd(&g_cursor[d4.x], 1);
    int p1 = atomicAdd(&g_cursor[d4.y], 1);
    int p2 = atomicAdd(&g_cursor[d4.z], 1);
    int p3 = atomicAdd(&g_cursor[d4.w], 1);
    g_col[p0] = s4.x;
    g_col[p1] = s4.y;
    g_col[p2] = s4.z;
    g_col[p3] = s4.w;
}

// ---------------- helpers ----------------
__device__ __forceinline__ void bf16_split2(float a, float b, uint32_t& hi, uint32_t& lo) {
    __nv_bfloat162 h = __floats2bfloat162_rn(a, b);
    hi = *(uint32_t*)&h;
    float ra = a - __bfloat162float(h.x);
    float rb = b - __bfloat162float(h.y);
    __nv_bfloat162 l = __floats2bfloat162_rn(ra, rb);
    lo = *(uint32_t*)&l;
}

__device__ __forceinline__ void mma_bf16(float* c, uint32_t a0, uint32_t a1,
                                         uint32_t a2, uint32_t a3,
                                         uint32_t b0, uint32_t b1) {
    asm volatile(
        "mma.sync.aligned.m16n8k16.row.col.f32.bf16.bf16.f32 "
        "{%0,%1,%2,%3}, {%4,%5,%6,%7}, {%8,%9}, {%0,%1,%2,%3};"
        : "+f"(c[0]), "+f"(c[1]), "+f"(c[2]), "+f"(c[3])
        : "r"(a0), "r"(a1), "r"(a2), "r"(a3), "r"(b0), "r"(b1));
}

__device__ __forceinline__ void cp16(uint32_t saddr, const void* gptr) {
    asm volatile("cp.async.ca.shared.global [%0], [%1], 16;" :: "r"(saddr), "l"(gptr));
}

// ---------------- fused GEMM1+GEMM2 (3xBF16 mma.sync, pipelined) ----------------
#define AS2 68
#define HS2 132
#define OFF_AL   (128 * AS2)
#define OFF_H1H  (2 * 128 * AS2)
#define OFF_H1L  (OFF_H1H + 128 * HS2)
#define OFF_STG  (OFF_H1L + 128 * HS2)
#define STG_SZ   (2 * 128 * 12)
#define SMEM_U32 (OFF_STG + 2 * STG_SZ)

__global__ __launch_bounds__(256) void k_gemm12(const __nv_bfloat16* __restrict__ a_hi,
                                                const __nv_bfloat16* __restrict__ a_lo,
                                                const __nv_bfloat16* __restrict__ w1h,
                                                const __nv_bfloat16* __restrict__ w1l,
                                                const __nv_bfloat16* __restrict__ w2h,
                                                const __nv_bfloat16* __restrict__ w2l,
                                                const float* __restrict__ b1,
                                                float* __restrict__ hs2) {
    extern __shared__ __align__(16) uint32_t sm[];

    const int tid  = threadIdx.x;
    const int lane = tid & 31;
    const int warp = tid >> 5;
    const int gid  = lane >> 2;
    const int tig  = lane & 3;
    const int warpM = warp & 3;
    const int warpN = warp >> 2;
    const int rowBase = blockIdx.x * 128;

    const uint32_t sb = (uint32_t)__cvta_generic_to_shared(sm);

    for (int u = tid; u < 4096; u += 256) {
        int p = u >> 11;
        int v = u & 2047;
        int r = v >> 4, ch = v & 15;
        const __nv_bfloat16* g = (p ? a_lo : a_hi) + (size_t)(rowBase + r) * 128 + ch * 8;
        uint32_t d = sb + (uint32_t)(((p ? OFF_AL : 0) + r * AS2 + ch * 4) << 2);
        cp16(d, g);
    }

    auto loadB = [&](int s, const __nv_bfloat16* bh, const __nv_bfloat16* bl,
                     int mBase, int Kb, int kBase) {
        int r = tid >> 1, ch = tid & 1;
        size_t go = (size_t)(mBase + r) * Kb + kBase + ch * 8;
        uint32_t d = sb + (uint32_t)((OFF_STG + s * STG_SZ + r * 12 + ch * 4) << 2);
        cp16(d, bh + go);
        cp16(d + (uint32_t)((128 * 12) << 2), bl + go);
    };

    float acc[2][8][4];

    // =================== phase 1: two column blocks of h1 ===================
    #pragma unroll 1
    for (int cb = 0; cb < 2; cb++) {
        #pragma unroll
        for (int mt = 0; mt < 2; mt++)
            #pragma unroll
            for (int nt = 0; nt < 8; nt++)
                #pragma unroll
                for (int j = 0; j < 4; j++) acc[mt][nt][j] = 0.f;

        loadB(0, w1h, w1l, cb * 128, 128, 0);
        asm volatile("cp.async.commit_group;");

        #pragma unroll 1
        for (int i = 0; i < 8; i++) {
            if (i < 7) {
                loadB((i + 1) & 1, w1h, w1l, cb * 128, 128, (i + 1) * 16);
                asm volatile("cp.async.commit_group;");
                asm volatile("cp.async.wait_group 1;");
            } else {
                asm volatile("cp.async.wait_group 0;");
            }
            __syncthreads();

            const uint32_t* Bh = &sm[OFF_STG + (i & 1) * STG_SZ];
            const uint32_t* Bl = Bh + 128 * 12;
            const int ks = i * 8;

            uint32_t ahi[2][4], alo[2][4];
            #pragma unroll
            for (int mt = 0; mt < 2; mt++) {
                int r0 = warpM * 32 + mt * 16 + gid;
                ahi[mt][0] = sm[r0 * AS2 + ks + tig];
                ahi[mt][1] = sm[(r0 + 8) * AS2 + ks + tig];
                ahi[mt][2] = sm[r0 * AS2 + ks + tig + 4];
                ahi[mt][3] = sm[(r0 + 8) * AS2 + ks + tig + 4];
                alo[mt][0] = sm[OFF_AL + r0 * AS2 + ks + tig];
                alo[mt][1] = sm[OFF_AL + (r0 + 8) * AS2 + ks + tig];
                alo[mt][2] = sm[OFF_AL + r0 * AS2 + ks + tig + 4];
                alo[mt][3] = sm[OFF_AL + (r0 + 8) * AS2 + ks + tig + 4];
            }
            #pragma unroll
            for (int nt = 0; nt < 8; nt++) {
                int c0 = warpN * 64 + nt * 8 + gid;
                uint32_t bh0 = Bh[c0 * 12 + tig], bh1 = Bh[c0 * 12 + tig + 4];
                uint32_t bl0 = Bl[c0 * 12 + tig], bl1 = Bl[c0 * 12 + tig + 4];
                #pragma unroll
                for (int mt = 0; mt < 2; mt++) {
                    mma_bf16(acc[mt][nt], ahi[mt][0], ahi[mt][1], ahi[mt][2], ahi[mt][3], bh0, bh1);
                    mma_bf16(acc[mt][nt], ahi[mt][0], ahi[mt][1], ahi[mt][2], ahi[mt][3], bl0, bl1);
                    mma_bf16(acc[mt][nt], alo[mt][0], alo[mt][1], alo[mt][2], alo[mt][3], bh0, bh1);
                }
            }
            __syncthreads();
        }

        // epilogue: relu + bias, split into H1 planes
        #pragma unroll
        for (int mt = 0; mt < 2; mt++) {
            int rl = warpM * 32 + mt * 16 + gid;
            #pragma unroll
            for (int nt = 0; nt < 8; nt++) {
                int col = cb * 128 + warpN * 64 + nt * 8 + 2 * tig;
                int cidx = col >> 1;
                float bb0 = b1[col], bb1 = b1[col + 1];
                float* c = acc[mt][nt];
                uint32_t h, l;
                float v0 = fmaxf(c[0] + bb0, 0.f), v1 = fmaxf(c[1] + bb1, 0.f);
                bf16_split2(v0, v1, h, l);
                sm[OFF_H1H + rl * HS2 + cidx] = h;
                sm[OFF_H1L + rl * HS2 + cidx] = l;
                v0 = fmaxf(c[2] + bb0, 0.f); v1 = fmaxf(c[3] + bb1, 0.f);
                bf16_split2(v0, v1, h, l);
                sm[OFF_H1H + (rl + 8) * HS2 + cidx] = h;
                sm[OFF_H1L + (rl + 8) * HS2 + cidx] = l;
            }
        }
    }

    // =================== phase 2: hs2 = dinv * (h1 @ W2) ===================
    #pragma unroll
    for (int mt = 0; mt < 2; mt++)
        #pragma unroll
        for (int nt = 0; nt < 8; nt++)
            #pragma unroll
            for (int j = 0; j < 4; j++) acc[mt][nt][j] = 0.f;

    loadB(0, w2h, w2l, 0, 256, 0);
    asm volatile("cp.async.commit_group;");

    #pragma unroll 1
    for (int i = 0; i < 16; i++) {
        if (i < 15) {
            loadB((i + 1) & 1, w2h, w2l, 0, 256, (i + 1) * 16);
            asm volatile("cp.async.commit_group;");
            asm volatile("cp.async.wait_group 1;");
        } else {
            asm volatile("cp.async.wait_group 0;");
        }
        __syncthreads();   // also orders H1 writes before first reads

        const uint32_t* Bh = &sm[OFF_STG + (i & 1) * STG_SZ];
        const uint32_t* Bl = Bh + 128 * 12;
        const int ks = i * 8;

        uint32_t ahi[2][4], alo[2][4];
        #pragma unroll
        for (int mt = 0; mt < 2; mt++) {
            int r0 = warpM * 32 + mt * 16 + gid;
            ahi[mt][0] = sm[OFF_H1H + r0 * HS2 + ks + tig];
            ahi[mt][1] = sm[OFF_H1H + (r0 + 8) * HS2 + ks + tig];
            ahi[mt][2] = sm[OFF_H1H + r0 * HS2 + ks + tig + 4];
            ahi[mt][3] = sm[OFF_H1H + (r0 + 8) * HS2 + ks + tig + 4];
            alo[mt][0] = sm[OFF_H1L + r0 * HS2 + ks + tig];
            alo[mt][1] = sm[OFF_H1L + (r0 + 8) * HS2 + ks + tig];
            alo[mt][2] = sm[OFF_H1L + r0 * HS2 + ks + tig + 4];
            alo[mt][3] = sm[OFF_H1L + (r0 + 8) * HS2 + ks + tig + 4];
        }
        #pragma unroll
        for (int nt = 0; nt < 8; nt++) {
            int c0 = warpN * 64 + nt * 8 + gid;
            uint32_t bh0 = Bh[c0 * 12 + tig], bh1 = Bh[c0 * 12 + tig + 4];
            uint32_t bl0 = Bl[c0 * 12 + tig], bl1 = Bl[c0 * 12 + tig + 4];
            #pragma unroll
            for (int mt = 0; mt < 2; mt++) {
                mma_bf16(acc[mt][nt], ahi[mt][0], ahi[mt][1], ahi[mt][2], ahi[mt][3], bh0, bh1);
                mma_bf16(acc[mt][nt], ahi[mt][0], ahi[mt][1], ahi[mt][2], ahi[mt][3], bl0, bl1);
                mma_bf16(acc[mt][nt], alo[mt][0], alo[mt][1], alo[mt][2], alo[mt][3], bh0, bh1);
            }
        }
        __syncthreads();
    }

    // epilogue: dinv scale -> global
    #pragma unroll
    for (int mt = 0; mt < 2; mt++) {
        int r0 = rowBase + warpM * 32 + mt * 16 + gid;
        #pragma unroll
        for (int nt = 0; nt < 8; nt++) {
            int col = warpN * 64 + nt * 8 + 2 * tig;
            float* c = acc[mt][nt];
            if (r0 < N_NODES) {
                float d = g_dinv[r0];
                *(float2*)&hs2[(size_t)r0 * 128 + col] = make_float2(c[0] * d, c[1] * d);
            }
            if (r0 + 8 < N_NODES) {
                float d = g_dinv[r0 + 8];
                *(float2*)&hs2[(size_t)(r0 + 8) * 128 + col] = make_float2(c[2] * d, c[3] * d);
            }
        }
    }
}

// ---------------- layer-0 aggregation -> split bf16 planes (2-wide) ----------------
__global__ __launch_bounds__(256) void k_agg0(const float* __restrict__ x) {
    int node = (blockIdx.x * blockDim.x + threadIdx.x) >> 5;
    int lane = threadIdx.x & 31;
    if (node >= N_NODES) return;

    float dself = g_dinv[node];
    float4 acc = *(const float4*)&x[(size_t)node * 128 + lane * 4];
    acc.x *= dself; acc.y *= dself; acc.z *= dself; acc.w *= dself;

    int e = g_rowptr[node], eEnd = g_rowptr[node + 1];
    for (; e + 1 < eEnd; e += 2) {
        int s0 = g_col[e], s1 = g_col[e + 1];
        float d0 = g_dinv[s0], d1 = g_dinv[s1];
        float4 x0 = *(const float4*)&x[(size_t)s0 * 128 + lane * 4];
        float4 x1 = *(const float4*)&x[(size_t)s1 * 128 + lane * 4];
        acc.x += x0.x * d0 + x1.x * d1;
        acc.y += x0.y * d0 + x1.y * d1;
        acc.z += x0.z * d0 + x1.z * d1;
        acc.w += x0.w * d0 + x1.w * d1;
    }
    if (e < eEnd) {
        int s0 = g_col[e];
        float d0 = g_dinv[s0];
        float4 x0 = *(const float4*)&x[(size_t)s0 * 128 + lane * 4];
        acc.x += x0.x * d0; acc.y += x0.y * d0;
        acc.z += x0.z * d0; acc.w += x0.w * d0;
    }

    acc.x *= dself; acc.y *= dself; acc.z *= dself; acc.w *= dself;
    uint32_t h01, l01, h23, l23;
    bf16_split2(acc.x, acc.y, h01, l01);
    bf16_split2(acc.z, acc.w, h23, l23);
    size_t o = (size_t)node * 128 + lane * 4;
    *(uint32_t*)&g_a0_hi[o]     = h01;
    *(uint32_t*)&g_a0_hi[o + 2] = h23;
    *(uint32_t*)&g_a0_lo[o]     = l01;
    *(uint32_t*)&g_a0_lo[o + 2] = l23;
}

// ---------------- layer-2 aggregation + fused layer-3 GEMM (2-wide) ----------------
__global__ __launch_bounds__(256) void k_agg_out(const float* __restrict__ b2,
                                                 const float* __restrict__ W3) {
    __shared__ float w3s[256];
    if (threadIdx.x < 256) w3s[threadIdx.x] = W3[threadIdx.x];
    __syncthreads();

    int node = (blockIdx.x * blockDim.x + threadIdx.x) >> 5;
    int lane = threadIdx.x & 31;
    if (node >= N_NODES) return;

    float4 acc = *(const float4*)&g_hs2[(size_t)node * 128 + lane * 4];
    int e = g_rowptr[node], eEnd = g_rowptr[node + 1];
    for (; e + 1 < eEnd; e += 2) {
        int s0 = g_col[e], s1 = g_col[e + 1];
        float4 x0 = *(const float4*)&g_hs2[(size_t)s0 * 128 + lane * 4];
        float4 x1 = *(const float4*)&g_hs2[(size_t)s1 * 128 + lane * 4];
        acc.x += x0.x + x1.x;
        acc.y += x0.y + x1.y;
        acc.z += x0.z + x1.z;
        acc.w += x0.w + x1.w;
    }
    if (e < eEnd) {
        int s0 = g_col[e];
        float4 x0 = *(const float4*)&g_hs2[(size_t)s0 * 128 + lane * 4];
        acc.x += x0.x; acc.y += x0.y; acc.z += x0.z; acc.w += x0.w;
    }

    float d = g_dinv[node];
    float4 b = *(const float4*)&b2[lane * 4];
    float o0 = fmaxf(acc.x * d + b.x, 0.f);
    float o1 = fmaxf(acc.y * d + b.y, 0.f);
    float o2 = fmaxf(acc.z * d + b.z, 0.f);
    float o3 = fmaxf(acc.w * d + b.w, 0.f);

    int c = lane * 4;
    float p0 = o0 * w3s[c * 2 + 0] + o1 * w3s[(c + 1) * 2 + 0]
             + o2 * w3s[(c + 2) * 2 + 0] + o3 * w3s[(c + 3) * 2 + 0];
    float p1 = o0 * w3s[c * 2 + 1] + o1 * w3s[(c + 1) * 2 + 1]
             + o2 * w3s[(c + 2) * 2 + 1] + o3 * w3s[(c + 3) * 2 + 1];
    #pragma unroll
    for (int off = 16; off; off >>= 1) {
        p0 += __shfl_down_sync(0xFFFFFFFFu, p0, off);
        p1 += __shfl_down_sync(0xFFFFFFFFu, p1, off);
    }
    if (lane == 0) {
        g_hs3[(size_t)node * 2 + 0] = p0 * d;
        g_hs3[(size_t)node * 2 + 1] = p1 * d;
    }
}

// ---------------- final aggregation + log_softmax (CH=2) ----------------
__global__ __launch_bounds__(256) void k_agg3(const float* __restrict__ b3,
                                              float* __restrict__ out) {
    int i = blockIdx.x * blockDim.x + threadIdx.x;
    if (i >= N_NODES) return;
    float2 acc = *(const float2*)&g_hs3[(size_t)i * 2];
    int e = g_rowptr[i], eE = g_rowptr[i + 1];
    for (; e < eE; e++) {
        int s = g_col[e];
        float2 x = *(const float2*)&g_hs3[(size_t)s * 2];
        acc.x += x.x;
        acc.y += x.y;
    }
    float d = g_dinv[i];
    float v0 = acc.x * d + b3[0];
    float v1 = acc.y * d + b3[1];
    float m = fmaxf(v0, v1);
    float lse = m + logf(expf(v0 - m) + expf(v1 - m));
    out[(size_t)i * 2 + 0] = v0 - lse;
    out[(size_t)i * 2 + 1] = v1 - lse;
}

// ---------------- launch ----------------
extern "C" void kernel_launch(void* const* d_in, const int* in_sizes, int n_in,
                              void* d_out, int out_size) {
    const float* x  = (const float*)d_in[0];
    const float* W1 = (const float*)d_in[1];
    const float* b1 = (const float*)d_in[2];
    const float* W2 = (const float*)d_in[3];
    const float* b2 = (const float*)d_in[4];
    const float* W3 = (const float*)d_in[5];
    const float* b3 = (const float*)d_in[6];
    const int* ei   = (const int*)d_in[7];   // int32 (JAX x64 disabled)
    const int* src  = ei;
    const int* dst  = ei + N_EDGES;
    float* out = (float*)d_out;

    __nv_bfloat16 *a0hi, *a0lo, *wt1hi, *wt1lo, *wt2hi, *wt2lo;
    float* hs2;
    cudaGetSymbolAddress((void**)&a0hi, g_a0_hi);
    cudaGetSymbolAddress((void**)&a0lo, g_a0_lo);
    cudaGetSymbolAddress((void**)&wt1hi, g_wt1_hi);
    cudaGetSymbolAddress((void**)&wt1lo, g_wt1_lo);
    cudaGetSymbolAddress((void**)&wt2hi, g_wt2_hi);
    cudaGetSymbolAddress((void**)&wt2lo, g_wt2_lo);
    cudaGetSymbolAddress((void**)&hs2, g_hs2);

    const int smemBytes = SMEM_U32 * 4;   // 229376 B (< 232448 opt-in cap)
    cudaFuncSetAttribute(k_gemm12, cudaFuncAttributeMaxDynamicSharedMemorySize, smemBytes);

    const int TB = 256;
    int edgeBlocks4 = (N_EDGES / 4 + TB - 1) / TB;
    int aggBlocks = (N_NODES * 32 + TB - 1) / TB;

    // 1: weight split + zero counts
    k_prep<<<256, TB>>>(W1, W2);
    // 2: degree count (int4, MLP=4)
    k_count<<<edgeBlocks4, TB>>>(dst);
    // 3-4: two-phase scan (phase 2 fused into apply) + dinv + cursor
    k_scan1<<<SCAN_BLKS, TB>>>();
    k_scan3<<<SCAN_BLKS, TB>>>();
    // 5: CSR fill (int4, MLP=4)
    k_fill<<<edgeBlocks4, TB>>>(src, dst);
    // 6: ax -> split planes [N,128]
    k_agg0<<<aggBlocks, TB>>>(x);
    // 7: h1 = relu(ax@W1+b1); hs2 = dinv*(h1@W2)  (fused, h1 stays in SMEM)
    k_gemm12<<<N_PAD / 128, TB, smemBytes>>>(a0hi, a0lo, wt1hi, wt1lo, wt2hi, wt2lo, b1, hs2);
    // 8: h2 = relu(dinv*(agg hs2)+b2); hs3 = dinv*(h2@W3)
    k_agg_out<<<aggBlocks, TB>>>(b2, W3);
    // 9: out = log_softmax
    k_agg3<<<SCAN_BLKS, TB>>>(b3, out);
}

// round 16
// speedup vs baseline: 1.7546x; 1.2140x over previous
#include <cuda_runtime.h>
#include <cuda_fp16.h>
#include <math.h>
#include <stdint.h>

#define N_NODES 50000
#define N_EDGES 600000
#define N_PAD   50048   // 391*128
#define IN_CH   128
#define HID1    256
#define HID2    128
#define SCAN_BLKS 196   // ceil(50000/256)

// ---------------- device scratch ----------------
__device__ int   g_counts[N_NODES];
__device__ int   g_rowptr[N_NODES + 1];
__device__ int   g_cursor[N_NODES];
__device__ float g_dinv[N_NODES];
__device__ int   g_col[N_EDGES];
__device__ int   g_bsum[SCAN_BLKS];

__device__ __align__(16) __half g_a0[(size_t)N_PAD * 128];     // fp16 activations
__device__ __align__(16) __half g_wt1_hi[256 * 128];
__device__ __align__(16) __half g_wt1_lo[256 * 128];
__device__ __align__(16) __half g_wt2_hi[128 * 256];
__device__ __align__(16) __half g_wt2_lo[128 * 256];
__device__ float g_hs2[(size_t)N_NODES * 128];
__device__ float g_hs3[(size_t)N_NODES * 2];

// ---------------- prep: split+transpose W1/W2 into fp16 planes, zero counts ----------------
__global__ __launch_bounds__(256) void k_prep(const float* __restrict__ W1,
                                              const float* __restrict__ W2) {
    int idx = blockIdx.x * 256 + threadIdx.x;   // 0 .. 65535
    if (idx < 128 * 256) {
        int k = idx >> 8, m = idx & 255;          // W1[k][m], K=128, M=256
        float v = W1[idx];
        __half h = __float2half_rn(v);
        __half l = __float2half_rn(v - __half2float(h));
        g_wt1_hi[m * 128 + k] = h;
        g_wt1_lo[m * 128 + k] = l;
    } else {
        int j = idx - 128 * 256;
        int k = j >> 7, m = j & 127;              // W2[k][m], K=256, M=128
        float v = W2[j];
        __half h = __float2half_rn(v);
        __half l = __float2half_rn(v - __half2float(h));
        g_wt2_hi[m * 256 + k] = h;
        g_wt2_lo[m * 256 + k] = l;
    }
    if (idx < N_NODES) g_counts[idx] = 0;
}

// ---------------- degree count, 4 edges/thread (MLP=4) ----------------
__global__ void k_count(const int* __restrict__ dst) {
    int t = blockIdx.x * blockDim.x + threadIdx.x;
    if (t * 4 >= N_EDGES) return;
    int4 d4 = *(const int4*)&dst[t * 4];
    atomicAdd(&g_counts[d4.x], 1);
    atomicAdd(&g_counts[d4.y], 1);
    atomicAdd(&g_counts[d4.z], 1);
    atomicAdd(&g_counts[d4.w], 1);
}

// ---------------- scan phase 1 ----------------
__global__ __launch_bounds__(256) void k_scan1() {
    __shared__ int sh[256];
    int b = blockIdx.x, t = threadIdx.x;
    int i = b * 256 + t;
    int v = (i < N_NODES) ? g_counts[i] : 0;
    sh[t] = v;
    __syncthreads();
    #pragma unroll
    for (int off = 1; off < 256; off <<= 1) {
        int u = (t >= off) ? sh[t - off] : 0;
        __syncthreads();
        sh[t] += u;
        __syncthreads();
    }
    if (i < N_NODES) g_rowptr[i + 1] = sh[t];
    if (t == 255) g_bsum[b] = sh[255];
}

// ---------------- scan phase 2 (fused predecessor reduction + apply) ----------------
__global__ __launch_bounds__(256) void k_scan3() {
    __shared__ int sh[8];
    __shared__ int s_prev;
    int b = blockIdx.x, t = threadIdx.x;

    int v = (t < b) ? g_bsum[t] : 0;
    #pragma unroll
    for (int o = 16; o; o >>= 1) v += __shfl_down_sync(0xFFFFFFFFu, v, o);
    if ((t & 31) == 0) sh[t >> 5] = v;
    __syncthreads();
    if (t < 8) {
        int w = sh[t];
        #pragma unroll
        for (int o = 4; o; o >>= 1) w += __shfl_down_sync(0x000000FFu, w, o);
        if (t == 0) s_prev = w;
    }
    __syncthreads();
    int prev = s_prev;

    int i = b * 256 + t;
    if (i < N_NODES) {
        int rp1 = g_rowptr[i + 1] + prev;
        g_rowptr[i + 1] = rp1;
        int c = g_counts[i];
        g_cursor[i] = rp1 - c;
        g_dinv[i] = rsqrtf((float)(c + 1));
    }
    if (i == 0) g_rowptr[0] = 0;
}

// ---------------- CSR fill, 4 edges/thread ----------------
__global__ void k_fill(const int* __restrict__ src,
                       const int* __restrict__ dst) {
    int t = blockIdx.x * blockDim.x + threadIdx.x;
    if (t * 4 >= N_EDGES) return;
    int4 s4 = *(const int4*)&src[t * 4];
    int4 d4 = *(const int4*)&dst[t * 4];
    int p0 = atomicAdd(&g_cursor[d4.x], 1);
    int p1 = atomicAdd(&g_cursor[d4.y], 1);
    int p2 = atomicAdd(&g_cursor[d4.z], 1);
    int p3 = atomicAdd(&g_cursor[d4.w], 1);
    g_col[p0] = s4.x;
    g_col[p1] = s4.y;
    g_col[p2] = s4.z;
    g_col[p3] = s4.w;
}

// ---------------- helpers ----------------
__device__ __forceinline__ void mma_f16(float* c, uint32_t a0, uint32_t a1,
                                        uint32_t a2, uint32_t a3,
                                        uint32_t b0, uint32_t b1) {
    asm volatile(
        "mma.sync.aligned.m16n8k16.row.col.f32.f16.f16.f32 "
        "{%0,%1,%2,%3}, {%4,%5,%6,%7}, {%8,%9}, {%0,%1,%2,%3};"
        : "+f"(c[0]), "+f"(c[1]), "+f"(c[2]), "+f"(c[3])
        : "r"(a0), "r"(a1), "r"(a2), "r"(a3), "r"(b0), "r"(b1));
}

__device__ __forceinline__ void cp16(uint32_t saddr, const void* gptr) {
    asm volatile("cp.async.ca.shared.global [%0], [%1], 16;" :: "r"(saddr), "l"(gptr));
}

__device__ __forceinline__ uint32_t pack_h2(float a, float b) {
    __half2 h = __floats2half2_rn(a, b);
    return *(uint32_t*)&h;
}

// ---------------- fused GEMM1+GEMM2 (2xFP16 mma.sync, pipelined) ----------------
// A (a0 / h1) single fp16 plane; W1/W2 fp16 hi+lo planes; 2 MMAs per pair.
// SMEM (u32): A [128 x 68] (64 data + pad), H1 [128 x 132] (128 data + pad),
//             STG [2 stages][hi,lo][128 x 12]
#define AS2 68
#define HS2 132
#define OFF_H1   (128 * AS2)
#define OFF_STG  (OFF_H1 + 128 * HS2)
#define STG_SZ   (2 * 128 * 12)
#define SMEM_U32 (OFF_STG + 2 * STG_SZ)   // 31744 u32 = 126976 B

__global__ __launch_bounds__(256) void k_gemm12(const __half* __restrict__ a0,
                                                const __half* __restrict__ w1h,
                                                const __half* __restrict__ w1l,
                                                const __half* __restrict__ w2h,
                                                const __half* __restrict__ w2l,
                                                const float* __restrict__ b1,
                                                float* __restrict__ hs2) {
    extern __shared__ __align__(16) uint32_t sm[];

    const int tid  = threadIdx.x;
    const int lane = tid & 31;
    const int warp = tid >> 5;
    const int gid  = lane >> 2;
    const int tig  = lane & 3;
    const int warpM = warp & 3;
    const int warpN = warp >> 2;
    const int rowBase = blockIdx.x * 128;

    const uint32_t sb = (uint32_t)__cvta_generic_to_shared(sm);

    // resident A plane: 128 rows x 128 fp16 = 2048 16B-chunks
    for (int u = tid; u < 2048; u += 256) {
        int r = u >> 4, ch = u & 15;
        const __half* g = a0 + (size_t)(rowBase + r) * 128 + ch * 8;
        uint32_t d = sb + (uint32_t)((r * AS2 + ch * 4) << 2);
        cp16(d, g);
    }

    // stream one 128x16 hi/lo W tile pair into stage s
    auto loadB = [&](int s, const __half* bh, const __half* bl,
                     int mBase, int Kb, int kBase) {
        int r = tid >> 1, ch = tid & 1;
        size_t go = (size_t)(mBase + r) * Kb + kBase + ch * 8;
        uint32_t d = sb + (uint32_t)((OFF_STG + s * STG_SZ + r * 12 + ch * 4) << 2);
        cp16(d, bh + go);
        cp16(d + (uint32_t)((128 * 12) << 2), bl + go);
    };

    float acc[2][8][4];

    // =================== phase 1: two column blocks of h1 ===================
    #pragma unroll 1
    for (int cb = 0; cb < 2; cb++) {
        #pragma unroll
        for (int mt = 0; mt < 2; mt++)
            #pragma unroll
            for (int nt = 0; nt < 8; nt++)
                #pragma unroll
                for (int j = 0; j < 4; j++) acc[mt][nt][j] = 0.f;

        loadB(0, w1h, w1l, cb * 128, 128, 0);
        asm volatile("cp.async.commit_group;");

        #pragma unroll 1
        for (int i = 0; i < 8; i++) {
            if (i < 7) {
                loadB((i + 1) & 1, w1h, w1l, cb * 128, 128, (i + 1) * 16);
                asm volatile("cp.async.commit_group;");
                asm volatile("cp.async.wait_group 1;");
            } else {
                asm volatile("cp.async.wait_group 0;");
            }
            __syncthreads();

            const uint32_t* Bh = &sm[OFF_STG + (i & 1) * STG_SZ];
            const uint32_t* Bl = Bh + 128 * 12;
            const int ks = i * 8;

            uint32_t a[2][4];
            #pragma unroll
            for (int mt = 0; mt < 2; mt++) {
                int r0 = warpM * 32 + mt * 16 + gid;
                a[mt][0] = sm[r0 * AS2 + ks + tig];
                a[mt][1] = sm[(r0 + 8) * AS2 + ks + tig];
                a[mt][2] = sm[r0 * AS2 + ks + tig + 4];
                a[mt][3] = sm[(r0 + 8) * AS2 + ks + tig + 4];
            }
            #pragma unroll
            for (int nt = 0; nt < 8; nt++) {
                int c0 = warpN * 64 + nt * 8 + gid;
                uint32_t bh0 = Bh[c0 * 12 + tig], bh1 = Bh[c0 * 12 + tig + 4];
                uint32_t bl0 = Bl[c0 * 12 + tig], bl1 = Bl[c0 * 12 + tig + 4];
                #pragma unroll
                for (int mt = 0; mt < 2; mt++) {
                    mma_f16(acc[mt][nt], a[mt][0], a[mt][1], a[mt][2], a[mt][3], bh0, bh1);
                    mma_f16(acc[mt][nt], a[mt][0], a[mt][1], a[mt][2], a[mt][3], bl0, bl1);
                }
            }
            __syncthreads();
        }

        // epilogue: relu + bias -> h1 fp16 plane in SMEM
        #pragma unroll
        for (int mt = 0; mt < 2; mt++) {
            int rl = warpM * 32 + mt * 16 + gid;
            #pragma unroll
            for (int nt = 0; nt < 8; nt++) {
                int col = cb * 128 + warpN * 64 + nt * 8 + 2 * tig;
                int cidx = col >> 1;
                float bb0 = b1[col], bb1 = b1[col + 1];
                float* c = acc[mt][nt];
                float v0 = fmaxf(c[0] + bb0, 0.f), v1 = fmaxf(c[1] + bb1, 0.f);
                sm[OFF_H1 + rl * HS2 + cidx] = pack_h2(v0, v1);
                v0 = fmaxf(c[2] + bb0, 0.f); v1 = fmaxf(c[3] + bb1, 0.f);
                sm[OFF_H1 + (rl + 8) * HS2 + cidx] = pack_h2(v0, v1);
            }
        }
    }

    // =================== phase 2: hs2 = dinv * (h1 @ W2) ===================
    #pragma unroll
    for (int mt = 0; mt < 2; mt++)
        #pragma unroll
        for (int nt = 0; nt < 8; nt++)
            #pragma unroll
            for (int j = 0; j < 4; j++) acc[mt][nt][j] = 0.f;

    loadB(0, w2h, w2l, 0, 256, 0);
    asm volatile("cp.async.commit_group;");

    #pragma unroll 1
    for (int i = 0; i < 16; i++) {
        if (i < 15) {
            loadB((i + 1) & 1, w2h, w2l, 0, 256, (i + 1) * 16);
            asm volatile("cp.async.commit_group;");
            asm volatile("cp.async.wait_group 1;");
        } else {
            asm volatile("cp.async.wait_group 0;");
        }
        __syncthreads();   // also orders H1 writes before first reads

        const uint32_t* Bh = &sm[OFF_STG + (i & 1) * STG_SZ];
        const uint32_t* Bl = Bh + 128 * 12;
        const int ks = i * 8;

        uint32_t a[2][4];
        #pragma unroll
        for (int mt = 0; mt < 2; mt++) {
            int r0 = warpM * 32 + mt * 16 + gid;
            a[mt][0] = sm[OFF_H1 + r0 * HS2 + ks + tig];
            a[mt][1] = sm[OFF_H1 + (r0 + 8) * HS2 + ks + tig];
            a[mt][2] = sm[OFF_H1 + r0 * HS2 + ks + tig + 4];
            a[mt][3] = sm[OFF_H1 + (r0 + 8) * HS2 + ks + tig + 4];
        }
        #pragma unroll
        for (int nt = 0; nt < 8; nt++) {
            int c0 = warpN * 64 + nt * 8 + gid;
            uint32_t bh0 = Bh[c0 * 12 + tig], bh1 = Bh[c0 * 12 + tig + 4];
            uint32_t bl0 = Bl[c0 * 12 + tig], bl1 = Bl[c0 * 12 + tig + 4];
            #pragma unroll
            for (int mt = 0; mt < 2; mt++) {
                mma_f16(acc[mt][nt], a[mt][0], a[mt][1], a[mt][2], a[mt][3], bh0, bh1);
                mma_f16(acc[mt][nt], a[mt][0], a[mt][1], a[mt][2], a[mt][3], bl0, bl1);
            }
        }
        __syncthreads();
    }

    // epilogue: dinv scale -> global
    #pragma unroll
    for (int mt = 0; mt < 2; mt++) {
        int r0 = rowBase + warpM * 32 + mt * 16 + gid;
        #pragma unroll
        for (int nt = 0; nt < 8; nt++) {
            int col = warpN * 64 + nt * 8 + 2 * tig;
            float* c = acc[mt][nt];
            if (r0 < N_NODES) {
                float d = g_dinv[r0];
                *(float2*)&hs2[(size_t)r0 * 128 + col] = make_float2(c[0] * d, c[1] * d);
            }
            if (r0 + 8 < N_NODES) {
                float d = g_dinv[r0 + 8];
                *(float2*)&hs2[(size_t)(r0 + 8) * 128 + col] = make_float2(c[2] * d, c[3] * d);
            }
        }
    }
}

// ---------------- layer-0 aggregation -> fp16 plane (2-wide) ----------------
__global__ __launch_bounds__(256) void k_agg0(const float* __restrict__ x) {
    int node = (blockIdx.x * blockDim.x + threadIdx.x) >> 5;
    int lane = threadIdx.x & 31;
    if (node >= N_NODES) return;

    float dself = g_dinv[node];
    float4 acc = *(const float4*)&x[(size_t)node * 128 + lane * 4];
    acc.x *= dself; acc.y *= dself; acc.z *= dself; acc.w *= dself;

    int e = g_rowptr[node], eEnd = g_rowptr[node + 1];
    for (; e + 1 < eEnd; e += 2) {
        int s0 = g_col[e], s1 = g_col[e + 1];
        float d0 = g_dinv[s0], d1 = g_dinv[s1];
        float4 x0 = *(const float4*)&x[(size_t)s0 * 128 + lane * 4];
        float4 x1 = *(const float4*)&x[(size_t)s1 * 128 + lane * 4];
        acc.x += x0.x * d0 + x1.x * d1;
        acc.y += x0.y * d0 + x1.y * d1;
        acc.z += x0.z * d0 + x1.z * d1;
        acc.w += x0.w * d0 + x1.w * d1;
    }
    if (e < eEnd) {
        int s0 = g_col[e];
        float d0 = g_dinv[s0];
        float4 x0 = *(const float4*)&x[(size_t)s0 * 128 + lane * 4];
        acc.x += x0.x * d0; acc.y += x0.y * d0;
        acc.z += x0.z * d0; acc.w += x0.w * d0;
    }

    acc.x *= dself; acc.y *= dself; acc.z *= dself; acc.w *= dself;
    uint32_t p01 = pack_h2(acc.x, acc.y);
    uint32_t p23 = pack_h2(acc.z, acc.w);
    size_t o = (size_t)node * 128 + lane * 4;
    *(uint32_t*)&g_a0[o]     = p01;
    *(uint32_t*)&g_a0[o + 2] = p23;
}

// ---------------- layer-2 aggregation + fused layer-3 GEMM (2-wide) ----------------
__global__ __launch_bounds__(256) void k_agg_out(const float* __restrict__ b2,
                                                 const float* __restrict__ W3) {
    __shared__ float w3s[256];
    if (threadIdx.x < 256) w3s[threadIdx.x] = W3[threadIdx.x];
    __syncthreads();

    int node = (blockIdx.x * blockDim.x + threadIdx.x) >> 5;
    int lane = threadIdx.x & 31;
    if (node >= N_NODES) return;

    float4 acc = *(const float4*)&g_hs2[(size_t)node * 128 + lane * 4];
    int e = g_rowptr[node], eEnd = g_rowptr[node + 1];
    for (; e + 1 < eEnd; e += 2) {
        int s0 = g_col[e], s1 = g_col[e + 1];
        float4 x0 = *(const float4*)&g_hs2[(size_t)s0 * 128 + lane * 4];
        float4 x1 = *(const float4*)&g_hs2[(size_t)s1 * 128 + lane * 4];
        acc.x += x0.x + x1.x;
        acc.y += x0.y + x1.y;
        acc.z += x0.z + x1.z;
        acc.w += x0.w + x1.w;
    }
    if (e < eEnd) {
        int s0 = g_col[e];
        float4 x0 = *(const float4*)&g_hs2[(size_t)s0 * 128 + lane * 4];
        acc.x += x0.x; acc.y += x0.y; acc.z += x0.z; acc.w += x0.w;
    }

    float d = g_dinv[node];
    float4 b = *(const float4*)&b2[lane * 4];
    float o0 = fmaxf(acc.x * d + b.x, 0.f);
    float o1 = fmaxf(acc.y * d + b.y, 0.f);
    float o2 = fmaxf(acc.z * d + b.z, 0.f);
    float o3 = fmaxf(acc.w * d + b.w, 0.f);

    int c = lane * 4;
    float p0 = o0 * w3s[c * 2 + 0] + o1 * w3s[(c + 1) * 2 + 0]
             + o2 * w3s[(c + 2) * 2 + 0] + o3 * w3s[(c + 3) * 2 + 0];
    float p1 = o0 * w3s[c * 2 + 1] + o1 * w3s[(c + 1) * 2 + 1]
             + o2 * w3s[(c + 2) * 2 + 1] + o3 * w3s[(c + 3) * 2 + 1];
    #pragma unroll
    for (int off = 16; off; off >>= 1) {
        p0 += __shfl_down_sync(0xFFFFFFFFu, p0, off);
        p1 += __shfl_down_sync(0xFFFFFFFFu, p1, off);
    }
    if (lane == 0) {
        g_hs3[(size_t)node * 2 + 0] = p0 * d;
        g_hs3[(size_t)node * 2 + 1] = p1 * d;
    }
}

// ---------------- final aggregation + log_softmax (CH=2) ----------------
__global__ __launch_bounds__(256) void k_agg3(const float* __restrict__ b3,
                                              float* __restrict__ out) {
    int i = blockIdx.x * blockDim.x + threadIdx.x;
    if (i >= N_NODES) return;
    float2 acc = *(const float2*)&g_hs3[(size_t)i * 2];
    int e = g_rowptr[i], eE = g_rowptr[i + 1];
    for (; e < eE; e++) {
        int s = g_col[e];
        float2 x = *(const float2*)&g_hs3[(size_t)s * 2];
        acc.x += x.x;
        acc.y += x.y;
    }
    float d = g_dinv[i];
    float v0 = acc.x * d + b3[0];
    float v1 = acc.y * d + b3[1];
    float m = fmaxf(v0, v1);
    float lse = m + logf(expf(v0 - m) + expf(v1 - m));
    out[(size_t)i * 2 + 0] = v0 - lse;
    out[(size_t)i * 2 + 1] = v1 - lse;
}

// ---------------- launch ----------------
extern "C" void kernel_launch(void* const* d_in, const int* in_sizes, int n_in,
                              void* d_out, int out_size) {
    const float* x  = (const float*)d_in[0];
    const float* W1 = (const float*)d_in[1];
    const float* b1 = (const float*)d_in[2];
    const float* W2 = (const float*)d_in[3];
    const float* b2 = (const float*)d_in[4];
    const float* W3 = (const float*)d_in[5];
    const float* b3 = (const float*)d_in[6];
    const int* ei   = (const int*)d_in[7];   // int32 (JAX x64 disabled)
    const int* src  = ei;
    const int* dst  = ei + N_EDGES;
    float* out = (float*)d_out;

    __half *a0, *wt1hi, *wt1lo, *wt2hi, *wt2lo;
    float* hs2;
    cudaGetSymbolAddress((void**)&a0, g_a0);
    cudaGetSymbolAddress((void**)&wt1hi, g_wt1_hi);
    cudaGetSymbolAddress((void**)&wt1lo, g_wt1_lo);
    cudaGetSymbolAddress((void**)&wt2hi, g_wt2_hi);
    cudaGetSymbolAddress((void**)&wt2lo, g_wt2_lo);
    cudaGetSymbolAddress((void**)&hs2, g_hs2);

    const int smemBytes = SMEM_U32 * 4;   // 126976 B
    cudaFuncSetAttribute(k_gemm12, cudaFuncAttributeMaxDynamicSharedMemorySize, smemBytes);

    const int TB = 256;
    int edgeBlocks4 = (N_EDGES / 4 + TB - 1) / TB;
    int aggBlocks = (N_NODES * 32 + TB - 1) / TB;

    // 1: weight split (fp16 hi/lo) + zero counts
    k_prep<<<256, TB>>>(W1, W2);
    // 2: degree count (int4, MLP=4)
    k_count<<<edgeBlocks4, TB>>>(dst);
    // 3-4: two-phase scan + dinv + cursor
    k_scan1<<<SCAN_BLKS, TB>>>();
    k_scan3<<<SCAN_BLKS, TB>>>();
    // 5: CSR fill (int4, MLP=4)
    k_fill<<<edgeBlocks4, TB>>>(src, dst);
    // 6: ax -> fp16 plane [N,128]
    k_agg0<<<aggBlocks, TB>>>(x);
    // 7: h1 = relu(ax@W1+b1); hs2 = dinv*(h1@W2)  (2xFP16 MMA, h1 stays in SMEM)
    k_gemm12<<<N_PAD / 128, TB, smemBytes>>>(a0, wt1hi, wt1lo, wt2hi, wt2lo, b1, hs2);
    // 8: h2 = relu(dinv*(agg hs2)+b2); hs3 = dinv*(h2@W3)
    k_agg_out<<<aggBlocks, TB>>>(b2, W3);
    // 9: out = log_softmax
    k_agg3<<<SCAN_BLKS, TB>>>(b3, out);
}

// round 17
// speedup vs baseline: 2.3200x; 1.3223x over previous
#include <cuda_runtime.h>
#include <cuda_fp16.h>
#include <math.h>
#include <stdint.h>

#define N_NODES 50000
#define N_EDGES 600000
#define N_PAD   50048   // 391*128
#define IN_CH   128
#define HID1    256
#define HID2    128
#define SCAN_BLKS 196   // ceil(50000/256)

// ---------------- device scratch ----------------
__device__ int   g_counts[N_NODES];
__device__ int   g_rowptr[N_NODES + 1];
__device__ int   g_cursor[N_NODES];
__device__ float g_dinv[N_NODES];
__device__ int   g_col[N_EDGES];
__device__ int   g_bsum[SCAN_BLKS];

__device__ __align__(16) __half g_x16[(size_t)N_PAD * 128];    // fp16 copy of x
__device__ __align__(16) __half g_a0[(size_t)N_PAD * 128];     // fp16 aggregated input
__device__ __align__(16) __half g_wt1[256 * 128];              // W1^T fp16
__device__ __align__(16) __half g_wt2[128 * 256];              // W2^T fp16
__device__ __align__(16) __half g_hs2[(size_t)N_PAD * 128];    // fp16 hs2
__device__ float g_hs3[(size_t)N_NODES * 2];

// ---------------- helpers ----------------
__device__ __forceinline__ uint32_t pack_h2(float a, float b) {
    __half2 h = __floats2half2_rn(a, b);
    return *(uint32_t*)&h;
}
__device__ __forceinline__ float2 unpack_h2(uint32_t p) {
    __half2 h = *(__half2*)&p;
    return __half22float2(h);
}

__device__ __forceinline__ void mma_f16(float* c, uint32_t a0, uint32_t a1,
                                        uint32_t a2, uint32_t a3,
                                        uint32_t b0, uint32_t b1) {
    asm volatile(
        "mma.sync.aligned.m16n8k16.row.col.f32.f16.f16.f32 "
        "{%0,%1,%2,%3}, {%4,%5,%6,%7}, {%8,%9}, {%0,%1,%2,%3};"
        : "+f"(c[0]), "+f"(c[1]), "+f"(c[2]), "+f"(c[3])
        : "r"(a0), "r"(a1), "r"(a2), "r"(a3), "r"(b0), "r"(b1));
}

__device__ __forceinline__ void cp16(uint32_t saddr, const void* gptr) {
    asm volatile("cp.async.ca.shared.global [%0], [%1], 16;" :: "r"(saddr), "l"(gptr));
}

// ---------------- prep: W1/W2 -> fp16 transposed, zero counts ----------------
__global__ __launch_bounds__(256) void k_prep(const float* __restrict__ W1,
                                              const float* __restrict__ W2) {
    int idx = blockIdx.x * 256 + threadIdx.x;   // 0 .. 65535
    if (idx < 128 * 256) {
        int k = idx >> 8, m = idx & 255;          // W1[k][m]
        g_wt1[m * 128 + k] = __float2half_rn(W1[idx]);
    } else {
        int j = idx - 128 * 256;
        int k = j >> 7, m = j & 127;              // W2[k][m]
        g_wt2[m * 256 + k] = __float2half_rn(W2[j]);
    }
    if (idx < N_NODES) g_counts[idx] = 0;
}

// ---------------- x -> fp16 ----------------
__global__ void k_xcvt(const float* __restrict__ x) {
    int idx = blockIdx.x * blockDim.x + threadIdx.x;   // float4 quad index
    if (idx >= N_NODES * 32) return;
    float4 v = *(const float4*)&x[(size_t)idx * 4];
    *(uint32_t*)&g_x16[(size_t)idx * 4]     = pack_h2(v.x, v.y);
    *(uint32_t*)&g_x16[(size_t)idx * 4 + 2] = pack_h2(v.z, v.w);
}

// ---------------- degree count, 4 edges/thread ----------------
__global__ void k_count(const int* __restrict__ dst) {
    int t = blockIdx.x * blockDim.x + threadIdx.x;
    if (t * 4 >= N_EDGES) return;
    int4 d4 = *(const int4*)&dst[t * 4];
    atomicAdd(&g_counts[d4.x], 1);
    atomicAdd(&g_counts[d4.y], 1);
    atomicAdd(&g_counts[d4.z], 1);
    atomicAdd(&g_counts[d4.w], 1);
}

// ---------------- scan phase 1 ----------------
__global__ __launch_bounds__(256) void k_scan1() {
    __shared__ int sh[256];
    int b = blockIdx.x, t = threadIdx.x;
    int i = b * 256 + t;
    int v = (i < N_NODES) ? g_counts[i] : 0;
    sh[t] = v;
    __syncthreads();
    #pragma unroll
    for (int off = 1; off < 256; off <<= 1) {
        int u = (t >= off) ? sh[t - off] : 0;
        __syncthreads();
        sh[t] += u;
        __syncthreads();
    }
    if (i < N_NODES) g_rowptr[i + 1] = sh[t];
    if (t == 255) g_bsum[b] = sh[255];
}

// ---------------- scan phase 2 (fused predecessor reduction + apply) ----------------
__global__ __launch_bounds__(256) void k_scan3() {
    __shared__ int sh[8];
    __shared__ int s_prev;
    int b = blockIdx.x, t = threadIdx.x;

    int v = (t < b) ? g_bsum[t] : 0;
    #pragma unroll
    for (int o = 16; o; o >>= 1) v += __shfl_down_sync(0xFFFFFFFFu, v, o);
    if ((t & 31) == 0) sh[t >> 5] = v;
    __syncthreads();
    if (t < 8) {
        int w = sh[t];
        #pragma unroll
        for (int o = 4; o; o >>= 1) w += __shfl_down_sync(0x000000FFu, w, o);
        if (t == 0) s_prev = w;
    }
    __syncthreads();
    int prev = s_prev;

    int i = b * 256 + t;
    if (i < N_NODES) {
        int rp1 = g_rowptr[i + 1] + prev;
        g_rowptr[i + 1] = rp1;
        int c = g_counts[i];
        g_cursor[i] = rp1 - c;
        g_dinv[i] = rsqrtf((float)(c + 1));
    }
    if (i == 0) g_rowptr[0] = 0;
}

// ---------------- CSR fill, 4 edges/thread ----------------
__global__ void k_fill(const int* __restrict__ src,
                       const int* __restrict__ dst) {
    int t = blockIdx.x * blockDim.x + threadIdx.x;
    if (t * 4 >= N_EDGES) return;
    int4 s4 = *(const int4*)&src[t * 4];
    int4 d4 = *(const int4*)&dst[t * 4];
    int p0 = atomicAdd(&g_cursor[d4.x], 1);
    int p1 = atomicAdd(&g_cursor[d4.y], 1);
    int p2 = atomicAdd(&g_cursor[d4.z], 1);
    int p3 = atomicAdd(&g_cursor[d4.w], 1);
    g_col[p0] = s4.x;
    g_col[p1] = s4.y;
    g_col[p2] = s4.z;
    g_col[p3] = s4.w;
}

// ---------------- fused GEMM1+GEMM2 (1xFP16 mma.sync, pipelined) ----------------
// SMEM (u32): A [128 x 68] fp16-pairs, H1 [128 x 132], STG [2 stages][128 x 12]
#define AS2 68
#define HS2 132
#define OFF_H1   (128 * AS2)
#define OFF_STG  (OFF_H1 + 128 * HS2)
#define STG_SZ   (128 * 12)
#define SMEM_U32 (OFF_STG + 2 * STG_SZ)   // 28672 u32 = 114688 B

__global__ __launch_bounds__(256) void k_gemm12(const __half* __restrict__ a0,
                                                const __half* __restrict__ w1,
                                                const __half* __restrict__ w2,
                                                const float* __restrict__ b1,
                                                __half* __restrict__ hs2) {
    extern __shared__ __align__(16) uint32_t sm[];

    const int tid  = threadIdx.x;
    const int lane = tid & 31;
    const int warp = tid >> 5;
    const int gid  = lane >> 2;
    const int tig  = lane & 3;
    const int warpM = warp & 3;
    const int warpN = warp >> 2;
    const int rowBase = blockIdx.x * 128;

    const uint32_t sb = (uint32_t)__cvta_generic_to_shared(sm);

    // resident A plane: 128 rows x 128 fp16 = 2048 16B-chunks
    for (int u = tid; u < 2048; u += 256) {
        int r = u >> 4, ch = u & 15;
        const __half* g = a0 + (size_t)(rowBase + r) * 128 + ch * 8;
        uint32_t d = sb + (uint32_t)((r * AS2 + ch * 4) << 2);
        cp16(d, g);
    }

    // stream one 128x16 fp16 W tile into stage s (256 chunks over 256 threads)
    auto loadB = [&](int s, const __half* b, int mBase, int Kb, int kBase) {
        int r = tid >> 1, ch = tid & 1;
        size_t go = (size_t)(mBase + r) * Kb + kBase + ch * 8;
        uint32_t d = sb + (uint32_t)((OFF_STG + s * STG_SZ + r * 12 + ch * 4) << 2);
        cp16(d, b + go);
    };

    float acc[2][8][4];

    // =================== phase 1: two column blocks of h1 ===================
    #pragma unroll 1
    for (int cb = 0; cb < 2; cb++) {
        #pragma unroll
        for (int mt = 0; mt < 2; mt++)
            #pragma unroll
            for (int nt = 0; nt < 8; nt++)
                #pragma unroll
                for (int j = 0; j < 4; j++) acc[mt][nt][j] = 0.f;

        loadB(0, w1, cb * 128, 128, 0);
        asm volatile("cp.async.commit_group;");

        #pragma unroll 1
        for (int i = 0; i < 8; i++) {
            if (i < 7) {
                loadB((i + 1) & 1, w1, cb * 128, 128, (i + 1) * 16);
                asm volatile("cp.async.commit_group;");
                asm volatile("cp.async.wait_group 1;");
            } else {
                asm volatile("cp.async.wait_group 0;");
            }
            __syncthreads();

            const uint32_t* B = &sm[OFF_STG + (i & 1) * STG_SZ];
            const int ks = i * 8;

            uint32_t a[2][4];
            #pragma unroll
            for (int mt = 0; mt < 2; mt++) {
                int r0 = warpM * 32 + mt * 16 + gid;
                a[mt][0] = sm[r0 * AS2 + ks + tig];
                a[mt][1] = sm[(r0 + 8) * AS2 + ks + tig];
                a[mt][2] = sm[r0 * AS2 + ks + tig + 4];
                a[mt][3] = sm[(r0 + 8) * AS2 + ks + tig + 4];
            }
            #pragma unroll
            for (int nt = 0; nt < 8; nt++) {
                int c0 = warpN * 64 + nt * 8 + gid;
                uint32_t b0 = B[c0 * 12 + tig], b1v = B[c0 * 12 + tig + 4];
                #pragma unroll
                for (int mt = 0; mt < 2; mt++)
                    mma_f16(acc[mt][nt], a[mt][0], a[mt][1], a[mt][2], a[mt][3], b0, b1v);
            }
            __syncthreads();
        }

        // epilogue: relu + bias -> h1 fp16 plane in SMEM
        #pragma unroll
        for (int mt = 0; mt < 2; mt++) {
            int rl = warpM * 32 + mt * 16 + gid;
            #pragma unroll
            for (int nt = 0; nt < 8; nt++) {
                int col = cb * 128 + warpN * 64 + nt * 8 + 2 * tig;
                int cidx = col >> 1;
                float bb0 = b1[col], bb1 = b1[col + 1];
                float* c = acc[mt][nt];
                float v0 = fmaxf(c[0] + bb0, 0.f), v1 = fmaxf(c[1] + bb1, 0.f);
                sm[OFF_H1 + rl * HS2 + cidx] = pack_h2(v0, v1);
                v0 = fmaxf(c[2] + bb0, 0.f); v1 = fmaxf(c[3] + bb1, 0.f);
                sm[OFF_H1 + (rl + 8) * HS2 + cidx] = pack_h2(v0, v1);
            }
        }
    }

    // =================== phase 2: hs2 = dinv * (h1 @ W2) -> fp16 ===================
    #pragma unroll
    for (int mt = 0; mt < 2; mt++)
        #pragma unroll
        for (int nt = 0; nt < 8; nt++)
            #pragma unroll
            for (int j = 0; j < 4; j++) acc[mt][nt][j] = 0.f;

    loadB(0, w2, 0, 256, 0);
    asm volatile("cp.async.commit_group;");

    #pragma unroll 1
    for (int i = 0; i < 16; i++) {
        if (i < 15) {
            loadB((i + 1) & 1, w2, 0, 256, (i + 1) * 16);
            asm volatile("cp.async.commit_group;");
            asm volatile("cp.async.wait_group 1;");
        } else {
            asm volatile("cp.async.wait_group 0;");
        }
        __syncthreads();   // also orders H1 writes before first reads

        const uint32_t* B = &sm[OFF_STG + (i & 1) * STG_SZ];
        const int ks = i * 8;

        uint32_t a[2][4];
        #pragma unroll
        for (int mt = 0; mt < 2; mt++) {
            int r0 = warpM * 32 + mt * 16 + gid;
            a[mt][0] = sm[OFF_H1 + r0 * HS2 + ks + tig];
            a[mt][1] = sm[OFF_H1 + (r0 + 8) * HS2 + ks + tig];
            a[mt][2] = sm[OFF_H1 + r0 * HS2 + ks + tig + 4];
            a[mt][3] = sm[OFF_H1 + (r0 + 8) * HS2 + ks + tig + 4];
        }
        #pragma unroll
        for (int nt = 0; nt < 8; nt++) {
            int c0 = warpN * 64 + nt * 8 + gid;
            uint32_t b0 = B[c0 * 12 + tig], b1v = B[c0 * 12 + tig + 4];
            #pragma unroll
            for (int mt = 0; mt < 2; mt++)
                mma_f16(acc[mt][nt], a[mt][0], a[mt][1], a[mt][2], a[mt][3], b0, b1v);
        }
        __syncthreads();
    }

    // epilogue: dinv scale -> global fp16
    #pragma unroll
    for (int mt = 0; mt < 2; mt++) {
        int r0 = rowBase + warpM * 32 + mt * 16 + gid;
        #pragma unroll
        for (int nt = 0; nt < 8; nt++) {
            int col = warpN * 64 + nt * 8 + 2 * tig;
            float* c = acc[mt][nt];
            if (r0 < N_NODES) {
                float d = g_dinv[r0];
                *(uint32_t*)&hs2[(size_t)r0 * 128 + col] = pack_h2(c[0] * d, c[1] * d);
            }
            if (r0 + 8 < N_NODES) {
                float d = g_dinv[r0 + 8];
                *(uint32_t*)&hs2[(size_t)(r0 + 8) * 128 + col] = pack_h2(c[2] * d, c[3] * d);
            }
        }
    }
}

// ---------------- layer-0 aggregation: gather fp16 x -> fp16 a0 (2-wide) ----------------
__global__ __launch_bounds__(256) void k_agg0() {
    int node = (blockIdx.x * blockDim.x + threadIdx.x) >> 5;
    int lane = threadIdx.x & 31;
    if (node >= N_NODES) return;

    float dself = g_dinv[node];
    size_t selfOff = (size_t)node * 128 + lane * 4;
    float2 sa = unpack_h2(*(const uint32_t*)&g_x16[selfOff]);
    float2 sbv = unpack_h2(*(const uint32_t*)&g_x16[selfOff + 2]);
    float4 acc = make_float4(sa.x * dself, sa.y * dself, sbv.x * dself, sbv.y * dself);

    int e = g_rowptr[node], eEnd = g_rowptr[node + 1];
    for (; e + 1 < eEnd; e += 2) {
        int s0 = g_col[e], s1 = g_col[e + 1];
        float d0 = g_dinv[s0], d1 = g_dinv[s1];
        size_t o0 = (size_t)s0 * 128 + lane * 4;
        size_t o1 = (size_t)s1 * 128 + lane * 4;
        float2 x0a = unpack_h2(*(const uint32_t*)&g_x16[o0]);
        float2 x0b = unpack_h2(*(const uint32_t*)&g_x16[o0 + 2]);
        float2 x1a = unpack_h2(*(const uint32_t*)&g_x16[o1]);
        float2 x1b = unpack_h2(*(const uint32_t*)&g_x16[o1 + 2]);
        acc.x += x0a.x * d0 + x1a.x * d1;
        acc.y += x0a.y * d0 + x1a.y * d1;
        acc.z += x0b.x * d0 + x1b.x * d1;
        acc.w += x0b.y * d0 + x1b.y * d1;
    }
    if (e < eEnd) {
        int s0 = g_col[e];
        float d0 = g_dinv[s0];
        size_t o0 = (size_t)s0 * 128 + lane * 4;
        float2 x0a = unpack_h2(*(const uint32_t*)&g_x16[o0]);
        float2 x0b = unpack_h2(*(const uint32_t*)&g_x16[o0 + 2]);
        acc.x += x0a.x * d0; acc.y += x0a.y * d0;
        acc.z += x0b.x * d0; acc.w += x0b.y * d0;
    }

    acc.x *= dself; acc.y *= dself; acc.z *= dself; acc.w *= dself;
    *(uint32_t*)&g_a0[selfOff]     = pack_h2(acc.x, acc.y);
    *(uint32_t*)&g_a0[selfOff + 2] = pack_h2(acc.z, acc.w);
}

// ---------------- layer-2 aggregation (fp16 gather) + fused layer-3 GEMM ----------------
__global__ __launch_bounds__(256) void k_agg_out(const float* __restrict__ b2,
                                                 const float* __restrict__ W3) {
    __shared__ float w3s[256];
    if (threadIdx.x < 256) w3s[threadIdx.x] = W3[threadIdx.x];
    __syncthreads();

    int node = (blockIdx.x * blockDim.x + threadIdx.x) >> 5;
    int lane = threadIdx.x & 31;
    if (node >= N_NODES) return;

    size_t selfOff = (size_t)node * 128 + lane * 4;
    float2 sa = unpack_h2(*(const uint32_t*)&g_hs2[selfOff]);
    float2 sbv = unpack_h2(*(const uint32_t*)&g_hs2[selfOff + 2]);
    float4 acc = make_float4(sa.x, sa.y, sbv.x, sbv.y);

    int e = g_rowptr[node], eEnd = g_rowptr[node + 1];
    for (; e + 1 < eEnd; e += 2) {
        int s0 = g_col[e], s1 = g_col[e + 1];
        size_t o0 = (size_t)s0 * 128 + lane * 4;
        size_t o1 = (size_t)s1 * 128 + lane * 4;
        float2 x0a = unpack_h2(*(const uint32_t*)&g_hs2[o0]);
        float2 x0b = unpack_h2(*(const uint32_t*)&g_hs2[o0 + 2]);
        float2 x1a = unpack_h2(*(const uint32_t*)&g_hs2[o1]);
        float2 x1b = unpack_h2(*(const uint32_t*)&g_hs2[o1 + 2]);
        acc.x += x0a.x + x1a.x;
        acc.y += x0a.y + x1a.y;
        acc.z += x0b.x + x1b.x;
        acc.w += x0b.y + x1b.y;
    }
    if (e < eEnd) {
        int s0 = g_col[e];
        size_t o0 = (size_t)s0 * 128 + lane * 4;
        float2 x0a = unpack_h2(*(const uint32_t*)&g_hs2[o0]);
        float2 x0b = unpack_h2(*(const uint32_t*)&g_hs2[o0 + 2]);
        acc.x += x0a.x; acc.y += x0a.y; acc.z += x0b.x; acc.w += x0b.y;
    }

    float d = g_dinv[node];
    float4 b = *(const float4*)&b2[lane * 4];
    float o0 = fmaxf(acc.x * d + b.x, 0.f);
    float o1 = fmaxf(acc.y * d + b.y, 0.f);
    float o2 = fmaxf(acc.z * d + b.z, 0.f);
    float o3 = fmaxf(acc.w * d + b.w, 0.f);

    int c = lane * 4;
    float p0 = o0 * w3s[c * 2 + 0] + o1 * w3s[(c + 1) * 2 + 0]
             + o2 * w3s[(c + 2) * 2 + 0] + o3 * w3s[(c + 3) * 2 + 0];
    float p1 = o0 * w3s[c * 2 + 1] + o1 * w3s[(c + 1) * 2 + 1]
             + o2 * w3s[(c + 2) * 2 + 1] + o3 * w3s[(c + 3) * 2 + 1];
    #pragma unroll
    for (int off = 16; off; off >>= 1) {
        p0 += __shfl_down_sync(0xFFFFFFFFu, p0, off);
        p1 += __shfl_down_sync(0xFFFFFFFFu, p1, off);
    }
    if (lane == 0) {
        g_hs3[(size_t)node * 2 + 0] = p0 * d;
        g_hs3[(size_t)node * 2 + 1] = p1 * d;
    }
}

// ---------------- final aggregation + log_softmax (CH=2) ----------------
__global__ __launch_bounds__(256) void k_agg3(const float* __restrict__ b3,
                                              float* __restrict__ out) {
    int i = blockIdx.x * blockDim.x + threadIdx.x;
    if (i >= N_NODES) return;
    float2 acc = *(const float2*)&g_hs3[(size_t)i * 2];
    int e = g_rowptr[i], eE = g_rowptr[i + 1];
    for (; e < eE; e++) {
        int s = g_col[e];
        float2 x = *(const float2*)&g_hs3[(size_t)s * 2];
        acc.x += x.x;
        acc.y += x.y;
    }
    float d = g_dinv[i];
    float v0 = acc.x * d + b3[0];
    float v1 = acc.y * d + b3[1];
    float m = fmaxf(v0, v1);
    float lse = m + logf(expf(v0 - m) + expf(v1 - m));
    out[(size_t)i * 2 + 0] = v0 - lse;
    out[(size_t)i * 2 + 1] = v1 - lse;
}

// ---------------- launch ----------------
extern "C" void kernel_launch(void* const* d_in, const int* in_sizes, int n_in,
                              void* d_out, int out_size) {
    const float* x  = (const float*)d_in[0];
    const float* W1 = (const float*)d_in[1];
    const float* b1 = (const float*)d_in[2];
    const float* W2 = (const float*)d_in[3];
    const float* b2 = (const float*)d_in[4];
    const float* W3 = (const float*)d_in[5];
    const float* b3 = (const float*)d_in[6];
    const int* ei   = (const int*)d_in[7];   // int32 (JAX x64 disabled)
    const int* src  = ei;
    const int* dst  = ei + N_EDGES;
    float* out = (float*)d_out;

    __half *a0, *wt1, *wt2, *hs2;
    cudaGetSymbolAddress((void**)&a0, g_a0);
    cudaGetSymbolAddress((void**)&wt1, g_wt1);
    cudaGetSymbolAddress((void**)&wt2, g_wt2);
    cudaGetSymbolAddress((void**)&hs2, g_hs2);

    const int smemBytes = SMEM_U32 * 4;   // 114688 B
    cudaFuncSetAttribute(k_gemm12, cudaFuncAttributeMaxDynamicSharedMemorySize, smemBytes);

    const int TB = 256;
    int edgeBlocks4 = (N_EDGES / 4 + TB - 1) / TB;
    int aggBlocks = (N_NODES * 32 + TB - 1) / TB;

    // 1: weight fp16 split + zero counts
    k_prep<<<256, TB>>>(W1, W2);
    // 2: x -> fp16
    k_xcvt<<<(N_NODES * 32 + TB - 1) / TB, TB>>>(x);
    // 3: degree count (int4, MLP=4)
    k_count<<<edgeBlocks4, TB>>>(dst);
    // 4-5: two-phase scan + dinv + cursor
    k_scan1<<<SCAN_BLKS, TB>>>();
    k_scan3<<<SCAN_BLKS, TB>>>();
    // 6: CSR fill (int4, MLP=4)
    k_fill<<<edgeBlocks4, TB>>>(src, dst);
    // 7: ax -> fp16 plane [N,128]  (fp16 gather)
    k_agg0<<<aggBlocks, TB>>>();
    // 8: h1 = relu(ax@W1+b1); hs2 = dinv*(h1@W2) -> fp16
    k_gemm12<<<N_PAD / 128, TB, smemBytes>>>(a0, wt1, wt2, b1, hs2);
    // 9: h2 = relu(dinv*(agg hs2)+b2); hs3 = dinv*(h2@W3)  (fp16 gather)
    k_agg_out<<<aggBlocks, TB>>>(b2, W3);
    // 10: out = log_softmax
    k_agg3<<<SCAN_BLKS, TB>>>(b3, out);
}